// round 4
// baseline (speedup 1.0000x reference)
#include <cuda_runtime.h>
#include <math.h>
#include <stdint.h>

#define BB 8
#define CIN 96
#define CC 192
#define HH 128
#define WW 128
#define WS 8
#define HEADS 8
#define HD 24
#define TT 131072
#define FF 768
#define KCONV 864   // 9*96

// ---------------- scratch ----------------
__device__ float g_nx[BB*CIN*HH*WW];
__device__ float g_nv[BB*CIN*HH*WW];
__device__ float g_xp[TT*CC];
__device__ float g_vp[TT*CC];
__device__ float g_xs[TT*CC];
__device__ float g_vs[TT*CC];
__device__ float g_q [TT*CC];
__device__ float g_kv[TT*2*CC];
__device__ float g_at[TT*CC];
__device__ float g_pr[TT*CC];
__device__ float g_l3[TT*CC];
__device__ float g_h1[(long)TT*FF];
__device__ float g_m [TT*CC];
__device__ float g_l4[TT*CC];
// weights: n-major, k-contiguous, k permuted in (k,k+4) pairs, tf32-rounded
__device__ float g_qwP [CC*CC];
__device__ float g_kvwP[2*CC*CC];
__device__ float g_apwP[CC*CC];
__device__ float g_f1wP[FF*CC];
__device__ float g_f2wP[CC*FF];
__device__ float g_cqwP[CC*KCONV];
__device__ float g_cvwP[CC*KCONV];

// ---------------- helpers ----------------
__device__ __forceinline__ uint32_t f2tf(float x) {
    uint32_t r; asm("cvt.rna.tf32.f32 %0, %1;" : "=r"(r) : "f"(x)); return r;
}
__device__ __forceinline__ float rnd(float x) { return __uint_as_float(f2tf(x)); }
// permuted position of channel c: within each 8-group, order (0,4,1,5,2,6,3,7)
__device__ __forceinline__ int pidx(int c) {
    return (c & ~7) | ((c & 3) << 1) | ((c >> 2) & 1);
}

__device__ __forceinline__ void mma_tf32(float* d, const uint32_t* a, const uint32_t* b, const float* c) {
    asm("mma.sync.aligned.m16n8k8.row.col.f32.tf32.tf32.f32 "
        "{%0,%1,%2,%3},{%4,%5,%6,%7},{%8,%9},{%10,%11,%12,%13};"
        : "=f"(d[0]), "=f"(d[1]), "=f"(d[2]), "=f"(d[3])
        : "r"(a[0]), "r"(a[1]), "r"(a[2]), "r"(a[3]),
          "r"(b[0]), "r"(b[1]),
          "f"(c[0]), "f"(c[1]), "f"(c[2]), "f"(c[3]));
}
__device__ __forceinline__ void cp16(uint32_t d, const void* s) {
    asm volatile("cp.async.cg.shared.global [%0], [%1], 16;" :: "r"(d), "l"(s));
}
__device__ __forceinline__ void cp16p(uint32_t d, const void* s, int sz) {
    asm volatile("cp.async.cg.shared.global [%0], [%1], 16, %2;" :: "r"(d), "l"(s), "r"(sz));
}
#define CP_COMMIT() asm volatile("cp.async.commit_group;")
#define CP_WAIT1()  asm volatile("cp.async.wait_group 1;")

// ---------------- fused weight prep ----------------
#define S1 (CC*CC)
#define S2 (2*CC*CC)
#define S4 (FF*CC)
#define S6 (KCONV*CC)
__global__ void prep_weights(
    const float* __restrict__ qw, const float* __restrict__ kvw, const float* __restrict__ apw,
    const float* __restrict__ f1w, const float* __restrict__ f2w,
    const float* __restrict__ cqw, const float* __restrict__ cvw,
    float* __restrict__ qwP, float* __restrict__ kvwP, float* __restrict__ apwP,
    float* __restrict__ f1wP, float* __restrict__ f2wP,
    float* __restrict__ cqwP, float* __restrict__ cvwP)
{
    long i = (long)blockIdx.x * 256 + threadIdx.x;
    long o = i;
    if (o < S1) { int n=o/CC, k=o%CC; qwP[(long)n*CC + pidx(k)] = rnd(qw[o]); return; }
    o -= S1;
    if (o < S2) { int n=o/CC, k=o%CC; kvwP[(long)n*CC + pidx(k)] = rnd(kvw[o]); return; }
    o -= S2;
    if (o < S1) { int n=o/CC, k=o%CC; apwP[(long)n*CC + pidx(k)] = rnd(apw[o]); return; }
    o -= S1;
    if (o < S4) { int n=o/CC, k=o%CC; f1wP[(long)n*CC + pidx(k)] = rnd(f1w[o]); return; }
    o -= S4;
    if (o < S4) { int n=o/FF, k=o%FF; f2wP[(long)n*FF + pidx(k)] = rnd(f2w[o]); return; }
    o -= S4;
    if (o < S6) { int oc=o/(CIN*9), rem=o%(CIN*9); int c=rem/9, kk=rem%9;
                  cqwP[(long)oc*KCONV + kk*CIN + pidx(c)] = rnd(cqw[o]); return; }
    o -= S6;
    if (o < S6) { int oc=o/(CIN*9), rem=o%(CIN*9); int c=rem/9, kk=rem%9;
                  cvwP[(long)oc*KCONV + kk*CIN + pidx(c)] = rnd(cvw[o]); return; }
}

// ---------------- NCHW -> NHWC (rounded, c permuted) ----------------
__global__ __launch_bounds__(256) void to_nhwc(const float* __restrict__ in, float* __restrict__ out) {
    __shared__ float tile[32][33];
    int by = blockIdx.z; int b = by >> 7, y = by & 127;
    int c0 = blockIdx.y * 32, x0 = blockIdx.x * 32;
    int tx = threadIdx.x, ty = threadIdx.y;
    #pragma unroll
    for (int i = ty; i < 32; i += 8)
        tile[i][tx] = in[((long)(b * CIN + c0 + i) * HH + y) * WW + x0 + tx];
    __syncthreads();
    #pragma unroll
    for (int i = ty; i < 32; i += 8)
        out[((long)(b * HH + y) * WW + x0 + i) * CIN + pidx(c0 + tx)] = rnd(tile[tx][i]);
}

// ---------------- tf32 MMA GEMM: perm-k layout, float2 fragment LDS ----------------
// block 128x64, 8 warps (4m x 2n), warp 32x32. K-tile 16, stride 24, double buffered.
#define SAs 24
template<bool BIAS, bool GELU, bool ROUND, bool PERMW>
__global__ __launch_bounds__(256) void mm_tf32(
    const float* __restrict__ A, const float* __restrict__ W,
    const float* __restrict__ bias, float* __restrict__ C,
    int M, int N, int K, float alpha)
{
    __shared__ float As[2][128*SAs];
    __shared__ float Bs[2][64*SAs];
    int tid = threadIdx.x;
    long bm = (long)blockIdx.y * 128;
    int bn = blockIdx.x * 64;
    int wid = tid >> 5, lane = tid & 31;
    int wm = wid >> 1, wn = wid & 1;
    int m0 = wm * 32, n0 = wn * 32;
    int g = lane >> 2, tg = lane & 3;

    int arow = tid >> 2, aseg = tid & 3;   // A: rows arow, arow+64 (p=0,1)
    // B: row tid>>2 (0..63), seg tid&3 — exactly 1 chunk/thread

    uint32_t sAa = (uint32_t)__cvta_generic_to_shared(&As[0][0]);
    uint32_t sBa = (uint32_t)__cvta_generic_to_shared(&Bs[0][0]);
    uint32_t dA0 = sAa + (arow * SAs + aseg * 4) * 4;
    uint32_t dA1 = sAa + ((arow + 64) * SAs + aseg * 4) * 4;
    uint32_t dB  = sBa + (arow * SAs + aseg * 4) * 4;
    const float* pA0 = A + (bm + arow) * K + aseg * 4;
    const float* pA1 = A + (bm + arow + 64) * K + aseg * 4;
    const float* pB  = W + (long)(bn + arow) * K + aseg * 4;
    const uint32_t stA = 128 * SAs * 4, stB = 64 * SAs * 4;

    float acc[2][4][4];
    #pragma unroll
    for (int i = 0; i < 2; i++)
        #pragma unroll
        for (int j = 0; j < 4; j++)
            #pragma unroll
            for (int r = 0; r < 4; r++) acc[i][j][r] = 0.f;

    cp16(dA0, pA0); cp16(dA1, pA1); cp16(dB, pB);
    CP_COMMIT();
    int NT = K / 16;
    for (int t = 0; t < NT; t++) {
        int buf = t & 1;
        if (t + 1 < NT) {
            int kt = (t + 1) * 16;
            int nb = buf ^ 1;
            cp16(dA0 + nb * stA, pA0 + kt);
            cp16(dA1 + nb * stA, pA1 + kt);
            cp16(dB  + nb * stB, pB + kt);
        }
        CP_COMMIT();
        CP_WAIT1();
        __syncthreads();
        const float* as = As[buf];
        const float* bs = Bs[buf];
        #pragma unroll
        for (int kk = 0; kk < 16; kk += 8) {
            int ko = kk + 2 * tg;
            float2 a00 = *(const float2*)&as[(m0 + g)      * SAs + ko];
            float2 a01 = *(const float2*)&as[(m0 + g + 8)  * SAs + ko];
            float2 a10 = *(const float2*)&as[(m0 + 16 + g) * SAs + ko];
            float2 a11 = *(const float2*)&as[(m0 + 24 + g) * SAs + ko];
            uint32_t af[2][4];
            af[0][0] = __float_as_uint(a00.x); af[0][1] = __float_as_uint(a01.x);
            af[0][2] = __float_as_uint(a00.y); af[0][3] = __float_as_uint(a01.y);
            af[1][0] = __float_as_uint(a10.x); af[1][1] = __float_as_uint(a11.x);
            af[1][2] = __float_as_uint(a10.y); af[1][3] = __float_as_uint(a11.y);
            #pragma unroll
            for (int j = 0; j < 4; j++) {
                float2 bv = *(const float2*)&bs[(n0 + j*8 + g) * SAs + ko];
                uint32_t bf[2] = { __float_as_uint(bv.x), __float_as_uint(bv.y) };
                mma_tf32(acc[0][j], af[0], bf, acc[0][j]);
                mma_tf32(acc[1][j], af[1], bf, acc[1][j]);
            }
        }
        __syncthreads();
    }
    #pragma unroll
    for (int i = 0; i < 2; i++) {
        long row0 = bm + m0 + i * 16 + g;
        #pragma unroll
        for (int j = 0; j < 4; j++) {
            int col = bn + n0 + j * 8 + 2 * tg;
            float b0 = 0.f, b1 = 0.f;
            if (BIAS) { b0 = bias[col]; b1 = bias[col + 1]; }
            #pragma unroll
            for (int half = 0; half < 2; half++) {
                long row = row0 + half * 8;
                float v0 = (acc[i][j][half * 2 + 0] + b0) * alpha;
                float v1 = (acc[i][j][half * 2 + 1] + b1) * alpha;
                if (GELU) {
                    v0 = 0.5f * v0 * (1.f + erff(v0 * 0.70710678118654752f));
                    v1 = 0.5f * v1 * (1.f + erff(v1 * 0.70710678118654752f));
                }
                if (ROUND) { v0 = rnd(v0); v1 = rnd(v1); }
                if (PERMW) {
                    C[row * N + pidx(col)]     = v0;
                    C[row * N + pidx(col + 1)] = v1;
                } else {
                    *(float2*)&C[row * N + col] = make_float2(v0, v1);
                }
            }
        }
    }
}

// ---------------- conv3x3 implicit GEMM, same scheme ----------------
__global__ __launch_bounds__(256) void conv_tf32(
    const float* __restrict__ nhwc, const float* __restrict__ W,
    const float* __restrict__ bias, float* __restrict__ C)
{
    __shared__ float As[2][128*SAs];
    __shared__ float Bs[2][64*SAs];
    const int N = CC;
    int tid = threadIdx.x;
    long bm = (long)blockIdx.y * 128;
    int bn = blockIdx.x * 64;
    int wid = tid >> 5, lane = tid & 31;
    int wm = wid >> 1, wn = wid & 1;
    int m0 = wm * 32, n0 = wn * 32;
    int g = lane >> 2, tg = lane & 3;

    int arow = tid >> 2, aseg = tid & 3;

    uint32_t sAa = (uint32_t)__cvta_generic_to_shared(&As[0][0]);
    uint32_t sBa = (uint32_t)__cvta_generic_to_shared(&Bs[0][0]);
    uint32_t dA0 = sAa + (arow * SAs + aseg * 4) * 4;
    uint32_t dA1 = sAa + ((arow + 64) * SAs + aseg * 4) * 4;
    uint32_t dB  = sBa + (arow * SAs + aseg * 4) * 4;
    const float* pB = W + (long)(bn + arow) * KCONV + aseg * 4;
    const uint32_t stA = 128 * SAs * 4, stB = 64 * SAs * 4;

    int xs_[2], ys_[2], bs_[2];
    #pragma unroll
    for (int h = 0; h < 2; h++) {
        long t = bm + arow + h * 64;
        int ix = t & 7, iy = (t >> 3) & 7, wx = (t >> 6) & 15, wy = (t >> 10) & 15;
        bs_[h] = (int)(t >> 14);
        xs_[h] = wx * 8 + ix;
        ys_[h] = wy * 8 + iy;
    }

    float acc[2][4][4];
    #pragma unroll
    for (int i = 0; i < 2; i++)
        #pragma unroll
        for (int j = 0; j < 4; j++)
            #pragma unroll
            for (int r = 0; r < 4; r++) acc[i][j][r] = 0.f;

    // prologue: tile 0 -> ky=0, kx=0, c0=0
    {
        #pragma unroll
        for (int h = 0; h < 2; h++) {
            int sy = ys_[h] - 1, sx = xs_[h] - 1;
            bool ok = (sy >= 0) && (sx >= 0);
            const float* src = ok ? &nhwc[((long)(bs_[h] * HH + sy) * WW + sx) * CIN + aseg * 4] : nhwc;
            cp16p((h ? dA1 : dA0), src, ok ? 16 : 0);
        }
        cp16(dB, pB);
        CP_COMMIT();
    }
    const int NT = KCONV / 16;   // 54
    for (int t = 0; t < NT; t++) {
        int buf = t & 1;
        if (t + 1 < NT) {
            int kt = (t + 1) * 16;
            int ky = kt / 288, rem = kt % 288;
            int kx = rem / 96, c0 = rem % 96;
            int nb = buf ^ 1;
            #pragma unroll
            for (int h = 0; h < 2; h++) {
                int sy = ys_[h] + ky - 1, sx = xs_[h] + kx - 1;
                bool ok = (sy >= 0) && (sy < HH) && (sx >= 0) && (sx < WW);
                const float* src = ok ? &nhwc[((long)(bs_[h] * HH + sy) * WW + sx) * CIN + c0 + aseg * 4] : nhwc;
                cp16p((h ? dA1 : dA0) + nb * stA, src, ok ? 16 : 0);
            }
            cp16(dB + nb * stB, pB + kt);
        }
        CP_COMMIT();
        CP_WAIT1();
        __syncthreads();
        const float* as = As[buf];
        const float* bs = Bs[buf];
        #pragma unroll
        for (int kk = 0; kk < 16; kk += 8) {
            int ko = kk + 2 * tg;
            float2 a00 = *(const float2*)&as[(m0 + g)      * SAs + ko];
            float2 a01 = *(const float2*)&as[(m0 + g + 8)  * SAs + ko];
            float2 a10 = *(const float2*)&as[(m0 + 16 + g) * SAs + ko];
            float2 a11 = *(const float2*)&as[(m0 + 24 + g) * SAs + ko];
            uint32_t af[2][4];
            af[0][0] = __float_as_uint(a00.x); af[0][1] = __float_as_uint(a01.x);
            af[0][2] = __float_as_uint(a00.y); af[0][3] = __float_as_uint(a01.y);
            af[1][0] = __float_as_uint(a10.x); af[1][1] = __float_as_uint(a11.x);
            af[1][2] = __float_as_uint(a10.y); af[1][3] = __float_as_uint(a11.y);
            #pragma unroll
            for (int j = 0; j < 4; j++) {
                float2 bv = *(const float2*)&bs[(n0 + j*8 + g) * SAs + ko];
                uint32_t bf[2] = { __float_as_uint(bv.x), __float_as_uint(bv.y) };
                mma_tf32(acc[0][j], af[0], bf, acc[0][j]);
                mma_tf32(acc[1][j], af[1], bf, acc[1][j]);
            }
        }
        __syncthreads();
    }
    #pragma unroll
    for (int i = 0; i < 2; i++) {
        long row0 = bm + m0 + i * 16 + g;
        #pragma unroll
        for (int j = 0; j < 4; j++) {
            int col = bn + n0 + j * 8 + 2 * tg;
            float b0 = bias[col], b1 = bias[col + 1];
            #pragma unroll
            for (int half = 0; half < 2; half++) {
                long row = row0 + half * 8;
                *(float2*)&C[row * N + col] =
                    make_float2(acc[i][j][half*2+0] + b0, acc[i][j][half*2+1] + b1);
            }
        }
    }
}

// ---------------- windowed attention (reads natural q/kv, writes perm) ----------------
__global__ __launch_bounds__(256) void attn_kernel(
    const float* __restrict__ q, const float* __restrict__ kv,
    const float* __restrict__ rpb, float* __restrict__ out)
{
    __shared__ float qs[64][25], ks[64][25], vs[64][25];
    __shared__ float sc[64][65];
    __shared__ float s_rpb[225][8];
    int w = blockIdx.x;
    int tid = threadIdx.x;
    long tb = (long)w * 64;
    for (int e = tid; e < 225 * 8; e += 256) s_rpb[e >> 3][e & 7] = rpb[e];
    for (int h = 0; h < HEADS; h++) {
        for (int e = tid; e < 64 * 24; e += 256) {
            int p = e / 24, d = e % 24;
            qs[p][d] = q [(tb + p) * CC          + h * HD + d];
            ks[p][d] = kv[(tb + p) * 2 * CC      + h * HD + d];
            vs[p][d] = kv[(tb + p) * 2 * CC + CC + h * HD + d];
        }
        __syncthreads();
        {
            int i = tid >> 2, l = tid & 3;
            #pragma unroll
            for (int jj = 0; jj < 16; jj++) {
                int j = l * 16 + jj;
                float s = 0.f;
                #pragma unroll
                for (int d = 0; d < 24; d++) s += qs[i][d] * ks[j][d];
                int ry = (i >> 3) - (j >> 3) + 7;
                int rx = (i & 7)  - (j & 7)  + 7;
                s += s_rpb[ry * 15 + rx][h];
                sc[i][j] = s;
            }
            float mx = -1e30f;
            #pragma unroll
            for (int jj = 0; jj < 16; jj++) mx = fmaxf(mx, sc[i][l * 16 + jj]);
            mx = fmaxf(mx, __shfl_xor_sync(~0u, mx, 1));
            mx = fmaxf(mx, __shfl_xor_sync(~0u, mx, 2));
            float sum = 0.f;
            #pragma unroll
            for (int jj = 0; jj < 16; jj++) {
                float e_ = __expf(sc[i][l * 16 + jj] - mx);
                sc[i][l * 16 + jj] = e_; sum += e_;
            }
            sum += __shfl_xor_sync(~0u, sum, 1);
            sum += __shfl_xor_sync(~0u, sum, 2);
            float inv = 1.f / sum;
            #pragma unroll
            for (int jj = 0; jj < 16; jj++) sc[i][l * 16 + jj] *= inv;
        }
        __syncthreads();
        for (int e = tid; e < 64 * 24; e += 256) {
            int p = e / 24, d = e % 24;
            float s = 0.f;
            #pragma unroll
            for (int j = 0; j < 64; j++) s += sc[p][j] * vs[j][d];
            out[(tb + p) * CC + pidx(h * HD + d)] = rnd(s);
        }
        __syncthreads();
    }
}

// ---------------- row LN ----------------
template<bool ROUND, bool PERM>
__global__ __launch_bounds__(256) void ln_rows_kernel(
    const float* __restrict__ in, const float* __restrict__ gamma,
    const float* __restrict__ beta, float* __restrict__ out)
{
    int warp = threadIdx.x >> 5, lane = threadIdx.x & 31;
    long row = (long)blockIdx.x * 8 + warp;
    const float* p = in + row * CC;
    float v[6];
    float sum = 0.f, sq = 0.f;
    #pragma unroll
    for (int k = 0; k < 6; k++) { v[k] = p[lane + k * 32]; sum += v[k]; sq += v[k] * v[k]; }
    #pragma unroll
    for (int o = 16; o > 0; o >>= 1) { sum += __shfl_xor_sync(~0u, sum, o); sq += __shfl_xor_sync(~0u, sq, o); }
    float mean = sum * (1.f / CC), var = sq * (1.f / CC) - mean * mean;
    float rstd = rsqrtf(var + 1e-5f);
    float* qo = out + row * CC;
    #pragma unroll
    for (int k = 0; k < 6; k++) {
        int c = lane + k * 32;
        float r = (v[k] - mean) * rstd * gamma[c] + beta[c];
        if (ROUND) r = rnd(r);
        qo[PERM ? pidx(c) : c] = r;
    }
}

// ---------------- token layout -> NCHW with residual ----------------
__global__ __launch_bounds__(256) void final_kernel(
    const float* __restrict__ mln, const float* __restrict__ xp,
    const float* __restrict__ vp, float* __restrict__ out)
{
    __shared__ float s[128][33];
    int bx = blockIdx.x;
    int cch = bx % 6;
    int by = bx / 6;
    int b = by >> 7, y = by & 127;
    int c0 = cch * 32;
    int tid = threadIdx.x;
    int wy = y >> 3, iy = y & 7;
    #pragma unroll
    for (int it = 0; it < 16; it++) {
        int e = tid + it * 256;
        int x = e >> 5, cl = e & 31;
        long t = (long)b * 16384 + (wy * 16 + (x >> 3)) * 64 + iy * 8 + (x & 7);
        long a = t * CC + c0 + cl;
        s[x][cl] = mln[a] + xp[a] + vp[a];
    }
    __syncthreads();
    #pragma unroll
    for (int it = 0; it < 16; it++) {
        int e = tid + it * 256;
        int x = e & 127, c = e >> 7;
        out[((long)(b * CC + c0 + c) * HH + y) * WW + x] = s[x][c];
    }
}

extern "C" void kernel_launch(void* const* d_in, const int* in_sizes, int n_in,
                              void* d_out, int out_size)
{
    const float* x    = (const float*)d_in[0];
    const float* v    = (const float*)d_in[1];
    const float* pq_w = (const float*)d_in[2];
    const float* pq_b = (const float*)d_in[3];
    const float* pv_w = (const float*)d_in[4];
    const float* pv_b = (const float*)d_in[5];
    const float* n1w  = (const float*)d_in[6];
    const float* n1b  = (const float*)d_in[7];
    const float* n2w  = (const float*)d_in[8];
    const float* n2b  = (const float*)d_in[9];
    const float* n3w  = (const float*)d_in[10];
    const float* n3b  = (const float*)d_in[11];
    const float* n4w  = (const float*)d_in[12];
    const float* n4b  = (const float*)d_in[13];
    const float* qw   = (const float*)d_in[14];
    const float* kvw  = (const float*)d_in[15];
    const float* apw  = (const float*)d_in[16];
    const float* apb  = (const float*)d_in[17];
    const float* rpb  = (const float*)d_in[18];
    const float* f1w  = (const float*)d_in[19];
    const float* f1b  = (const float*)d_in[20];
    const float* f2w  = (const float*)d_in[21];
    const float* f2b  = (const float*)d_in[22];
    float* out = (float*)d_out;
    (void)in_sizes; (void)n_in; (void)out_size;

    float *nx,*nv,*xp,*vp,*xs,*vs,*q,*kv,*at,*pr,*l3,*h1,*m,*l4;
    float *qwP,*kvwP,*apwP,*f1wP,*f2wP,*cqwP,*cvwP;
    cudaGetSymbolAddress((void**)&nx, g_nx);
    cudaGetSymbolAddress((void**)&nv, g_nv);
    cudaGetSymbolAddress((void**)&xp, g_xp);
    cudaGetSymbolAddress((void**)&vp, g_vp);
    cudaGetSymbolAddress((void**)&xs, g_xs);
    cudaGetSymbolAddress((void**)&vs, g_vs);
    cudaGetSymbolAddress((void**)&q , g_q );
    cudaGetSymbolAddress((void**)&kv, g_kv);
    cudaGetSymbolAddress((void**)&at, g_at);
    cudaGetSymbolAddress((void**)&pr, g_pr);
    cudaGetSymbolAddress((void**)&l3, g_l3);
    cudaGetSymbolAddress((void**)&h1, g_h1);
    cudaGetSymbolAddress((void**)&m , g_m );
    cudaGetSymbolAddress((void**)&l4, g_l4);
    cudaGetSymbolAddress((void**)&qwP , g_qwP );
    cudaGetSymbolAddress((void**)&kvwP, g_kvwP);
    cudaGetSymbolAddress((void**)&apwP, g_apwP);
    cudaGetSymbolAddress((void**)&f1wP, g_f1wP);
    cudaGetSymbolAddress((void**)&f2wP, g_f2wP);
    cudaGetSymbolAddress((void**)&cqwP, g_cqwP);
    cudaGetSymbolAddress((void**)&cvwP, g_cvwP);

    const float SCALE = 0.20412414523193154f;  // 24^-0.5

    long totalW = (long)S1 + S2 + S1 + S4 + S4 + S6 + S6;
    prep_weights<<<(int)((totalW + 255) / 256), 256>>>(
        qw, kvw, apw, f1w, f2w, pq_w, pv_w,
        qwP, kvwP, apwP, f1wP, f2wP, cqwP, cvwP);

    to_nhwc<<<dim3(4,3,1024),dim3(32,8)>>>(x, nx);
    to_nhwc<<<dim3(4,3,1024),dim3(32,8)>>>(v, nv);

    conv_tf32<<<dim3(3,1024),256>>>(nx, cqwP, pq_b, xp);
    conv_tf32<<<dim3(3,1024),256>>>(nv, cvwP, pv_b, vp);

    ln_rows_kernel<true,true><<<16384,256>>>(xp, n1w, n1b, xs);
    ln_rows_kernel<true,true><<<16384,256>>>(vp, n2w, n2b, vs);

    mm_tf32<false,false,false,false><<<dim3(3,1024),256>>>(xs, qwP , nullptr, q , TT, CC,   CC, SCALE);
    mm_tf32<false,false,false,false><<<dim3(6,1024),256>>>(vs, kvwP, nullptr, kv, TT, 2*CC, CC, 1.f);

    attn_kernel<<<2048,256>>>(q, kv, rpb, at);

    mm_tf32<true,false,false,false><<<dim3(3,1024),256>>>(at, apwP, apb, pr, TT, CC, CC, 1.f);

    ln_rows_kernel<true,true><<<16384,256>>>(pr, n3w, n3b, l3);

    mm_tf32<true,true ,true ,true ><<<dim3(12,1024),256>>>(l3, f1wP, f1b, h1, TT, FF, CC, 1.f);
    mm_tf32<true,false,false,false><<<dim3(3,1024),256>>>(h1, f2wP, f2b, m , TT, CC, FF, 2.f);

    ln_rows_kernel<false,false><<<16384,256>>>(m, n4w, n4b, l4);

    final_kernel<<<6144,256>>>(l4, xp, vp, out);
}

// round 5
// speedup vs baseline: 1.0515x; 1.0515x over previous
#include <cuda_runtime.h>
#include <math.h>
#include <stdint.h>

#define BB 8
#define CIN 96
#define CC 192
#define HH 128
#define WW 128
#define WS 8
#define HEADS 8
#define HD 24
#define TT 131072
#define FF 768
#define KCONV 864   // 9*96

// ---------------- scratch ----------------
__device__ float g_nx[BB*CIN*HH*WW];
__device__ float g_nv[BB*CIN*HH*WW];
__device__ float g_xp[TT*CC];
__device__ float g_vp[TT*CC];
__device__ float g_xs[TT*CC];
__device__ float g_vs[TT*CC];
__device__ float g_q [TT*CC];
__device__ float g_kv[TT*2*CC];
__device__ float g_at[TT*CC];
__device__ float g_pr[TT*CC];
__device__ float g_l3[TT*CC];
__device__ float g_h1[(long)TT*FF];
__device__ float g_m [TT*CC];
__device__ float g_l4[TT*CC];
// weights: n-major, k-contiguous, k permuted in (k,k+4) pairs, tf32-rounded
__device__ float g_qwP [CC*CC];
__device__ float g_kvwP[2*CC*CC];
__device__ float g_apwP[CC*CC];
__device__ float g_f1wP[FF*CC];
__device__ float g_f2wP[CC*FF];
__device__ float g_cqwP[CC*KCONV];
__device__ float g_cvwP[CC*KCONV];

// ---------------- helpers ----------------
__device__ __forceinline__ uint32_t f2tf(float x) {
    uint32_t r; asm("cvt.rna.tf32.f32 %0, %1;" : "=r"(r) : "f"(x)); return r;
}
__device__ __forceinline__ float rnd(float x) { return __uint_as_float(f2tf(x)); }
__device__ __forceinline__ int pidx(int c) {
    return (c & ~7) | ((c & 3) << 1) | ((c >> 2) & 1);
}

__device__ __forceinline__ void mma_tf32(float* d, const uint32_t* a, const uint32_t* b, const float* c) {
    asm("mma.sync.aligned.m16n8k8.row.col.f32.tf32.tf32.f32 "
        "{%0,%1,%2,%3},{%4,%5,%6,%7},{%8,%9},{%10,%11,%12,%13};"
        : "=f"(d[0]), "=f"(d[1]), "=f"(d[2]), "=f"(d[3])
        : "r"(a[0]), "r"(a[1]), "r"(a[2]), "r"(a[3]),
          "r"(b[0]), "r"(b[1]),
          "f"(c[0]), "f"(c[1]), "f"(c[2]), "f"(c[3]));
}
__device__ __forceinline__ void cp16(uint32_t d, const void* s) {
    asm volatile("cp.async.cg.shared.global [%0], [%1], 16;" :: "r"(d), "l"(s));
}
__device__ __forceinline__ void cp16p(uint32_t d, const void* s, int sz) {
    asm volatile("cp.async.cg.shared.global [%0], [%1], 16, %2;" :: "r"(d), "l"(s), "r"(sz));
}
#define CP_COMMIT() asm volatile("cp.async.commit_group;")
#define CP_WAIT1()  asm volatile("cp.async.wait_group 1;")

// ---------------- fused weight prep ----------------
#define S1 (CC*CC)
#define S2 (2*CC*CC)
#define S4 (FF*CC)
#define S6 (KCONV*CC)
__global__ void prep_weights(
    const float* __restrict__ qw, const float* __restrict__ kvw, const float* __restrict__ apw,
    const float* __restrict__ f1w, const float* __restrict__ f2w,
    const float* __restrict__ cqw, const float* __restrict__ cvw,
    float* __restrict__ qwP, float* __restrict__ kvwP, float* __restrict__ apwP,
    float* __restrict__ f1wP, float* __restrict__ f2wP,
    float* __restrict__ cqwP, float* __restrict__ cvwP)
{
    long i = (long)blockIdx.x * 256 + threadIdx.x;
    long o = i;
    if (o < S1) { int n=o/CC, k=o%CC; qwP[(long)n*CC + pidx(k)] = rnd(qw[o]); return; }
    o -= S1;
    if (o < S2) { int n=o/CC, k=o%CC; kvwP[(long)n*CC + pidx(k)] = rnd(kvw[o]); return; }
    o -= S2;
    if (o < S1) { int n=o/CC, k=o%CC; apwP[(long)n*CC + pidx(k)] = rnd(apw[o]); return; }
    o -= S1;
    if (o < S4) { int n=o/CC, k=o%CC; f1wP[(long)n*CC + pidx(k)] = rnd(f1w[o]); return; }
    o -= S4;
    if (o < S4) { int n=o/FF, k=o%FF; f2wP[(long)n*FF + pidx(k)] = rnd(f2w[o]); return; }
    o -= S4;
    if (o < S6) { int oc=o/(CIN*9), rem=o%(CIN*9); int c=rem/9, kk=rem%9;
                  cqwP[(long)oc*KCONV + kk*CIN + pidx(c)] = rnd(cqw[o]); return; }
    o -= S6;
    if (o < S6) { int oc=o/(CIN*9), rem=o%(CIN*9); int c=rem/9, kk=rem%9;
                  cvwP[(long)oc*KCONV + kk*CIN + pidx(c)] = rnd(cvw[o]); return; }
}

// ---------------- NCHW -> NHWC (rounded, c permuted) ----------------
__global__ __launch_bounds__(256) void to_nhwc(const float* __restrict__ in, float* __restrict__ out) {
    __shared__ float tile[32][33];
    int by = blockIdx.z; int b = by >> 7, y = by & 127;
    int c0 = blockIdx.y * 32, x0 = blockIdx.x * 32;
    int tx = threadIdx.x, ty = threadIdx.y;
    #pragma unroll
    for (int i = ty; i < 32; i += 8)
        tile[i][tx] = in[((long)(b * CIN + c0 + i) * HH + y) * WW + x0 + tx];
    __syncthreads();
    #pragma unroll
    for (int i = ty; i < 32; i += 8)
        out[((long)(b * HH + y) * WW + x0 + i) * CIN + pidx(c0 + tx)] = rnd(tile[tx][i]);
}

// ================= tf32 MMA GEMM: block 256x64, warp 64x32, swizzled smem ==========
// smem: A 256x16 words, B 64x16 words, chunk swizzle c' = c ^ (row&3). 2 stages = 40KB.
template<bool BIAS, bool GELU, bool ROUND, bool PERMW>
__global__ __launch_bounds__(256, 2) void mm_tf32(
    const float* __restrict__ A, const float* __restrict__ W,
    const float* __restrict__ bias, float* __restrict__ C,
    int M, int N, int K, float alpha)
{
    __shared__ float As[2][256*16];
    __shared__ float Bs[2][64*16];
    int tid = threadIdx.x;
    long bm = (long)blockIdx.y * 256;
    int bn = blockIdx.x * 64;
    int wid = tid >> 5, lane = tid & 31;
    int wm = wid >> 1, wn = wid & 1;
    int m0 = wm * 64, n0 = wn * 32;
    int g = lane >> 2, tg = lane & 3;

    int ar = tid >> 2, aseg = tid & 3;
    int asw = aseg ^ (ar & 3);

    uint32_t sAa = (uint32_t)__cvta_generic_to_shared(&As[0][0]);
    uint32_t sBa = (uint32_t)__cvta_generic_to_shared(&Bs[0][0]);
    uint32_t dA = sAa + (ar * 16 + asw * 4) * 4;
    uint32_t dB = sBa + (ar * 16 + asw * 4) * 4;
    const float* pA = A + (bm + ar) * K + aseg * 4;
    const float* pB = W + (long)(bn + ar) * K + aseg * 4;
    const uint32_t stA = 256 * 16 * 4, stB = 64 * 16 * 4;
    const uint32_t rA = 64 * 16 * 4;   // byte stride between row-groups in smem
    const long     gA = (long)64 * K;  // row-group stride in global

    // fragment smem word-offset constants
    int fo0 = (((tg >> 1) ^ (g & 3)) << 2) + ((tg & 1) << 1);
    int fo1 = fo0 ^ 8;

    float acc[4][4][4];
    #pragma unroll
    for (int i = 0; i < 4; i++)
        #pragma unroll
        for (int j = 0; j < 4; j++)
            #pragma unroll
            for (int r = 0; r < 4; r++) acc[i][j][r] = 0.f;

    #pragma unroll
    for (int h = 0; h < 4; h++) cp16(dA + h * rA, pA + h * gA);
    cp16(dB, pB);
    CP_COMMIT();
    int NT = K / 16;
    for (int t = 0; t < NT; t++) {
        int buf = t & 1;
        if (t + 1 < NT) {
            int kt = (t + 1) * 16;
            int nb = buf ^ 1;
            #pragma unroll
            for (int h = 0; h < 4; h++) cp16(dA + nb * stA + h * rA, pA + kt + h * gA);
            cp16(dB + nb * stB, pB + kt);
        }
        CP_COMMIT();
        CP_WAIT1();
        __syncthreads();
        const float* as = As[buf];
        const float* bs = Bs[buf];
        #pragma unroll
        for (int kk = 0; kk < 2; kk++) {
            int fo = kk ? fo1 : fo0;
            uint32_t af[4][4];
            #pragma unroll
            for (int i = 0; i < 4; i++) {
                float2 aLo = *(const float2*)&as[(m0 + i*16 + g)     * 16 + fo];
                float2 aHi = *(const float2*)&as[(m0 + i*16 + g + 8) * 16 + fo];
                af[i][0] = __float_as_uint(aLo.x); af[i][1] = __float_as_uint(aHi.x);
                af[i][2] = __float_as_uint(aLo.y); af[i][3] = __float_as_uint(aHi.y);
            }
            #pragma unroll
            for (int j = 0; j < 4; j++) {
                float2 bv = *(const float2*)&bs[(n0 + j*8 + g) * 16 + fo];
                uint32_t bf[2] = { __float_as_uint(bv.x), __float_as_uint(bv.y) };
                #pragma unroll
                for (int i = 0; i < 4; i++)
                    mma_tf32(acc[i][j], af[i], bf, acc[i][j]);
            }
        }
        __syncthreads();
    }
    #pragma unroll
    for (int i = 0; i < 4; i++) {
        long row0 = bm + m0 + i * 16 + g;
        #pragma unroll
        for (int j = 0; j < 4; j++) {
            int col = bn + n0 + j * 8 + 2 * tg;
            float b0 = 0.f, b1 = 0.f;
            if (BIAS) { b0 = bias[col]; b1 = bias[col + 1]; }
            #pragma unroll
            for (int half = 0; half < 2; half++) {
                long row = row0 + half * 8;
                float v0 = (acc[i][j][half * 2 + 0] + b0) * alpha;
                float v1 = (acc[i][j][half * 2 + 1] + b1) * alpha;
                if (GELU) {
                    v0 = 0.5f * v0 * (1.f + erff(v0 * 0.70710678118654752f));
                    v1 = 0.5f * v1 * (1.f + erff(v1 * 0.70710678118654752f));
                }
                if (ROUND) { v0 = rnd(v0); v1 = rnd(v1); }
                if (PERMW) {
                    C[row * N + pidx(col)]     = v0;
                    C[row * N + pidx(col + 1)] = v1;
                } else {
                    *(float2*)&C[row * N + col] = make_float2(v0, v1);
                }
            }
        }
    }
}

// ================= conv3x3 implicit GEMM: 256x64, same scheme =================
__global__ __launch_bounds__(256, 2) void conv_tf32(
    const float* __restrict__ nhwc, const float* __restrict__ W,
    const float* __restrict__ bias, float* __restrict__ C)
{
    __shared__ float As[2][256*16];
    __shared__ float Bs[2][64*16];
    const int N = CC;
    int tid = threadIdx.x;
    long bm = (long)blockIdx.y * 256;
    int bn = blockIdx.x * 64;
    int wid = tid >> 5, lane = tid & 31;
    int wm = wid >> 1, wn = wid & 1;
    int m0 = wm * 64, n0 = wn * 32;
    int g = lane >> 2, tg = lane & 3;

    int ar = tid >> 2, aseg = tid & 3;
    int asw = aseg ^ (ar & 3);

    uint32_t sAa = (uint32_t)__cvta_generic_to_shared(&As[0][0]);
    uint32_t sBa = (uint32_t)__cvta_generic_to_shared(&Bs[0][0]);
    uint32_t dA = sAa + (ar * 16 + asw * 4) * 4;
    uint32_t dB = sBa + (ar * 16 + asw * 4) * 4;
    const float* pB = W + (long)(bn + ar) * KCONV + aseg * 4;
    const uint32_t stA = 256 * 16 * 4, stB = 64 * 16 * 4;
    const uint32_t rA = 64 * 16 * 4;

    int fo0 = (((tg >> 1) ^ (g & 3)) << 2) + ((tg & 1) << 1);
    int fo1 = fo0 ^ 8;

    int xs_[4], ys_[4], bs_[4];
    #pragma unroll
    for (int h = 0; h < 4; h++) {
        long t = bm + ar + h * 64;
        int ix = t & 7, iy = (t >> 3) & 7, wx = (t >> 6) & 15, wy = (t >> 10) & 15;
        bs_[h] = (int)(t >> 14);
        xs_[h] = wx * 8 + ix;
        ys_[h] = wy * 8 + iy;
    }

    float acc[4][4][4];
    #pragma unroll
    for (int i = 0; i < 4; i++)
        #pragma unroll
        for (int j = 0; j < 4; j++)
            #pragma unroll
            for (int r = 0; r < 4; r++) acc[i][j][r] = 0.f;

    // prologue: tile 0 -> ky=0, kx=0, c0=0
    {
        #pragma unroll
        for (int h = 0; h < 4; h++) {
            int sy = ys_[h] - 1, sx = xs_[h] - 1;
            bool ok = (sy >= 0) && (sx >= 0);
            const float* src = ok ? &nhwc[((long)(bs_[h] * HH + sy) * WW + sx) * CIN + aseg * 4] : nhwc;
            cp16p(dA + h * rA, src, ok ? 16 : 0);
        }
        cp16(dB, pB);
        CP_COMMIT();
    }
    const int NT = KCONV / 16;   // 54
    for (int t = 0; t < NT; t++) {
        int buf = t & 1;
        if (t + 1 < NT) {
            int kt = (t + 1) * 16;
            int ky = kt / 288, rem = kt % 288;
            int kx = rem / 96, c0 = rem % 96;
            int nb = buf ^ 1;
            #pragma unroll
            for (int h = 0; h < 4; h++) {
                int sy = ys_[h] + ky - 1, sx = xs_[h] + kx - 1;
                bool ok = (sy >= 0) && (sy < HH) && (sx >= 0) && (sx < WW);
                const float* src = ok ? &nhwc[((long)(bs_[h] * HH + sy) * WW + sx) * CIN + c0 + aseg * 4] : nhwc;
                cp16p(dA + nb * stA + h * rA, src, ok ? 16 : 0);
            }
            cp16(dB + nb * stB, pB + kt);
        }
        CP_COMMIT();
        CP_WAIT1();
        __syncthreads();
        const float* as = As[buf];
        const float* bs = Bs[buf];
        #pragma unroll
        for (int kk = 0; kk < 2; kk++) {
            int fo = kk ? fo1 : fo0;
            uint32_t af[4][4];
            #pragma unroll
            for (int i = 0; i < 4; i++) {
                float2 aLo = *(const float2*)&as[(m0 + i*16 + g)     * 16 + fo];
                float2 aHi = *(const float2*)&as[(m0 + i*16 + g + 8) * 16 + fo];
                af[i][0] = __float_as_uint(aLo.x); af[i][1] = __float_as_uint(aHi.x);
                af[i][2] = __float_as_uint(aLo.y); af[i][3] = __float_as_uint(aHi.y);
            }
            #pragma unroll
            for (int j = 0; j < 4; j++) {
                float2 bv = *(const float2*)&bs[(n0 + j*8 + g) * 16 + fo];
                uint32_t bf[2] = { __float_as_uint(bv.x), __float_as_uint(bv.y) };
                #pragma unroll
                for (int i = 0; i < 4; i++)
                    mma_tf32(acc[i][j], af[i], bf, acc[i][j]);
            }
        }
        __syncthreads();
    }
    #pragma unroll
    for (int i = 0; i < 4; i++) {
        long row0 = bm + m0 + i * 16 + g;
        #pragma unroll
        for (int j = 0; j < 4; j++) {
            int col = bn + n0 + j * 8 + 2 * tg;
            float b0 = bias[col], b1 = bias[col + 1];
            #pragma unroll
            for (int half = 0; half < 2; half++) {
                long row = row0 + half * 8;
                *(float2*)&C[row * N + col] =
                    make_float2(acc[i][j][half*2+0] + b0, acc[i][j][half*2+1] + b1);
            }
        }
    }
}

// ---------------- windowed attention (reads natural q/kv, writes perm) ----------------
__global__ __launch_bounds__(256) void attn_kernel(
    const float* __restrict__ q, const float* __restrict__ kv,
    const float* __restrict__ rpb, float* __restrict__ out)
{
    __shared__ float qs[64][25], ks[64][25], vs[64][25];
    __shared__ float sc[64][65];
    __shared__ float s_rpb[225][8];
    int w = blockIdx.x;
    int tid = threadIdx.x;
    long tb = (long)w * 64;
    for (int e = tid; e < 225 * 8; e += 256) s_rpb[e >> 3][e & 7] = rpb[e];
    for (int h = 0; h < HEADS; h++) {
        for (int e = tid; e < 64 * 24; e += 256) {
            int p = e / 24, d = e % 24;
            qs[p][d] = q [(tb + p) * CC          + h * HD + d];
            ks[p][d] = kv[(tb + p) * 2 * CC      + h * HD + d];
            vs[p][d] = kv[(tb + p) * 2 * CC + CC + h * HD + d];
        }
        __syncthreads();
        {
            int i = tid >> 2, l = tid & 3;
            #pragma unroll
            for (int jj = 0; jj < 16; jj++) {
                int j = l * 16 + jj;
                float s = 0.f;
                #pragma unroll
                for (int d = 0; d < 24; d++) s += qs[i][d] * ks[j][d];
                int ry = (i >> 3) - (j >> 3) + 7;
                int rx = (i & 7)  - (j & 7)  + 7;
                s += s_rpb[ry * 15 + rx][h];
                sc[i][j] = s;
            }
            float mx = -1e30f;
            #pragma unroll
            for (int jj = 0; jj < 16; jj++) mx = fmaxf(mx, sc[i][l * 16 + jj]);
            mx = fmaxf(mx, __shfl_xor_sync(~0u, mx, 1));
            mx = fmaxf(mx, __shfl_xor_sync(~0u, mx, 2));
            float sum = 0.f;
            #pragma unroll
            for (int jj = 0; jj < 16; jj++) {
                float e_ = __expf(sc[i][l * 16 + jj] - mx);
                sc[i][l * 16 + jj] = e_; sum += e_;
            }
            sum += __shfl_xor_sync(~0u, sum, 1);
            sum += __shfl_xor_sync(~0u, sum, 2);
            float inv = 1.f / sum;
            #pragma unroll
            for (int jj = 0; jj < 16; jj++) sc[i][l * 16 + jj] *= inv;
        }
        __syncthreads();
        for (int e = tid; e < 64 * 24; e += 256) {
            int p = e / 24, d = e % 24;
            float s = 0.f;
            #pragma unroll
            for (int j = 0; j < 64; j++) s += sc[p][j] * vs[j][d];
            out[(tb + p) * CC + pidx(h * HD + d)] = rnd(s);
        }
        __syncthreads();
    }
}

// ---------------- row LN ----------------
template<bool ROUND, bool PERM>
__global__ __launch_bounds__(256) void ln_rows_kernel(
    const float* __restrict__ in, const float* __restrict__ gamma,
    const float* __restrict__ beta, float* __restrict__ out)
{
    int warp = threadIdx.x >> 5, lane = threadIdx.x & 31;
    long row = (long)blockIdx.x * 8 + warp;
    const float* p = in + row * CC;
    float v[6];
    float sum = 0.f, sq = 0.f;
    #pragma unroll
    for (int k = 0; k < 6; k++) { v[k] = p[lane + k * 32]; sum += v[k]; sq += v[k] * v[k]; }
    #pragma unroll
    for (int o = 16; o > 0; o >>= 1) { sum += __shfl_xor_sync(~0u, sum, o); sq += __shfl_xor_sync(~0u, sq, o); }
    float mean = sum * (1.f / CC), var = sq * (1.f / CC) - mean * mean;
    float rstd = rsqrtf(var + 1e-5f);
    float* qo = out + row * CC;
    #pragma unroll
    for (int k = 0; k < 6; k++) {
        int c = lane + k * 32;
        float r = (v[k] - mean) * rstd * gamma[c] + beta[c];
        if (ROUND) r = rnd(r);
        qo[PERM ? pidx(c) : c] = r;
    }
}

// ---------------- token layout -> NCHW with residual ----------------
__global__ __launch_bounds__(256) void final_kernel(
    const float* __restrict__ mln, const float* __restrict__ xp,
    const float* __restrict__ vp, float* __restrict__ out)
{
    __shared__ float s[128][33];
    int bx = blockIdx.x;
    int cch = bx % 6;
    int by = bx / 6;
    int b = by >> 7, y = by & 127;
    int c0 = cch * 32;
    int tid = threadIdx.x;
    int wy = y >> 3, iy = y & 7;
    #pragma unroll
    for (int it = 0; it < 16; it++) {
        int e = tid + it * 256;
        int x = e >> 5, cl = e & 31;
        long t = (long)b * 16384 + (wy * 16 + (x >> 3)) * 64 + iy * 8 + (x & 7);
        long a = t * CC + c0 + cl;
        s[x][cl] = mln[a] + xp[a] + vp[a];
    }
    __syncthreads();
    #pragma unroll
    for (int it = 0; it < 16; it++) {
        int e = tid + it * 256;
        int x = e & 127, c = e >> 7;
        out[((long)(b * CC + c0 + c) * HH + y) * WW + x] = s[x][c];
    }
}

extern "C" void kernel_launch(void* const* d_in, const int* in_sizes, int n_in,
                              void* d_out, int out_size)
{
    const float* x    = (const float*)d_in[0];
    const float* v    = (const float*)d_in[1];
    const float* pq_w = (const float*)d_in[2];
    const float* pq_b = (const float*)d_in[3];
    const float* pv_w = (const float*)d_in[4];
    const float* pv_b = (const float*)d_in[5];
    const float* n1w  = (const float*)d_in[6];
    const float* n1b  = (const float*)d_in[7];
    const float* n2w  = (const float*)d_in[8];
    const float* n2b  = (const float*)d_in[9];
    const float* n3w  = (const float*)d_in[10];
    const float* n3b  = (const float*)d_in[11];
    const float* n4w  = (const float*)d_in[12];
    const float* n4b  = (const float*)d_in[13];
    const float* qw   = (const float*)d_in[14];
    const float* kvw  = (const float*)d_in[15];
    const float* apw  = (const float*)d_in[16];
    const float* apb  = (const float*)d_in[17];
    const float* rpb  = (const float*)d_in[18];
    const float* f1w  = (const float*)d_in[19];
    const float* f1b  = (const float*)d_in[20];
    const float* f2w  = (const float*)d_in[21];
    const float* f2b  = (const float*)d_in[22];
    float* out = (float*)d_out;
    (void)in_sizes; (void)n_in; (void)out_size;

    float *nx,*nv,*xp,*vp,*xs,*vs,*q,*kv,*at,*pr,*l3,*h1,*m,*l4;
    float *qwP,*kvwP,*apwP,*f1wP,*f2wP,*cqwP,*cvwP;
    cudaGetSymbolAddress((void**)&nx, g_nx);
    cudaGetSymbolAddress((void**)&nv, g_nv);
    cudaGetSymbolAddress((void**)&xp, g_xp);
    cudaGetSymbolAddress((void**)&vp, g_vp);
    cudaGetSymbolAddress((void**)&xs, g_xs);
    cudaGetSymbolAddress((void**)&vs, g_vs);
    cudaGetSymbolAddress((void**)&q , g_q );
    cudaGetSymbolAddress((void**)&kv, g_kv);
    cudaGetSymbolAddress((void**)&at, g_at);
    cudaGetSymbolAddress((void**)&pr, g_pr);
    cudaGetSymbolAddress((void**)&l3, g_l3);
    cudaGetSymbolAddress((void**)&h1, g_h1);
    cudaGetSymbolAddress((void**)&m , g_m );
    cudaGetSymbolAddress((void**)&l4, g_l4);
    cudaGetSymbolAddress((void**)&qwP , g_qwP );
    cudaGetSymbolAddress((void**)&kvwP, g_kvwP);
    cudaGetSymbolAddress((void**)&apwP, g_apwP);
    cudaGetSymbolAddress((void**)&f1wP, g_f1wP);
    cudaGetSymbolAddress((void**)&f2wP, g_f2wP);
    cudaGetSymbolAddress((void**)&cqwP, g_cqwP);
    cudaGetSymbolAddress((void**)&cvwP, g_cvwP);

    const float SCALE = 0.20412414523193154f;  // 24^-0.5

    long totalW = (long)S1 + S2 + S1 + S4 + S4 + S6 + S6;
    prep_weights<<<(int)((totalW + 255) / 256), 256>>>(
        qw, kvw, apw, f1w, f2w, pq_w, pv_w,
        qwP, kvwP, apwP, f1wP, f2wP, cqwP, cvwP);

    to_nhwc<<<dim3(4,3,1024),dim3(32,8)>>>(x, nx);
    to_nhwc<<<dim3(4,3,1024),dim3(32,8)>>>(v, nv);

    conv_tf32<<<dim3(3,512),256>>>(nx, cqwP, pq_b, xp);
    conv_tf32<<<dim3(3,512),256>>>(nv, cvwP, pv_b, vp);

    ln_rows_kernel<true,true><<<16384,256>>>(xp, n1w, n1b, xs);
    ln_rows_kernel<true,true><<<16384,256>>>(vp, n2w, n2b, vs);

    mm_tf32<false,false,false,false><<<dim3(3,512),256>>>(xs, qwP , nullptr, q , TT, CC,   CC, SCALE);
    mm_tf32<false,false,false,false><<<dim3(6,512),256>>>(vs, kvwP, nullptr, kv, TT, 2*CC, CC, 1.f);

    attn_kernel<<<2048,256>>>(q, kv, rpb, at);

    mm_tf32<true,false,false,false><<<dim3(3,512),256>>>(at, apwP, apb, pr, TT, CC, CC, 1.f);

    ln_rows_kernel<true,true><<<16384,256>>>(pr, n3w, n3b, l3);

    mm_tf32<true,true ,true ,true ><<<dim3(12,512),256>>>(l3, f1wP, f1b, h1, TT, FF, CC, 1.f);
    mm_tf32<true,false,false,false><<<dim3(3,512),256>>>(h1, f2wP, f2b, m , TT, CC, FF, 2.f);

    ln_rows_kernel<false,false><<<16384,256>>>(m, n4w, n4b, l4);

    final_kernel<<<6144,256>>>(l4, xp, vp, out);
}

// round 6
// speedup vs baseline: 1.0851x; 1.0319x over previous
#include <cuda_runtime.h>
#include <math.h>
#include <stdint.h>

#define BB 8
#define CIN 96
#define CC 192
#define HH 128
#define WW 128
#define WS 8
#define HEADS 8
#define HD 24
#define TT 131072
#define FF 768
#define KCONV 864   // 9*96

// pipeline
#define ST 4
#define AWORDS (256*16)
#define BWORDS (64*16)
#define SMEMB (ST*(AWORDS+BWORDS)*4)

// ---------------- scratch ----------------
__device__ float g_nx[BB*CIN*HH*WW];
__device__ float g_nv[BB*CIN*HH*WW];
__device__ float g_xp[TT*CC];
__device__ float g_vp[TT*CC];
__device__ float g_xs[TT*CC];
__device__ float g_vs[TT*CC];
__device__ float g_q [TT*CC];
__device__ float g_kv[TT*2*CC];
__device__ float g_at[TT*CC];
__device__ float g_pr[TT*CC];
__device__ float g_l3[TT*CC];
__device__ float g_h1[(long)TT*FF];
__device__ float g_m [TT*CC];
__device__ float g_l4[TT*CC];
// weights: n-major, k-contiguous, k permuted in (k,k+4) pairs, tf32-rounded
__device__ float g_qwP [CC*CC];
__device__ float g_kvwP[2*CC*CC];
__device__ float g_apwP[CC*CC];
__device__ float g_f1wP[FF*CC];
__device__ float g_f2wP[CC*FF];
__device__ float g_cqwP[CC*KCONV];
__device__ float g_cvwP[CC*KCONV];

// ---------------- helpers ----------------
__device__ __forceinline__ uint32_t f2tf(float x) {
    uint32_t r; asm("cvt.rna.tf32.f32 %0, %1;" : "=r"(r) : "f"(x)); return r;
}
__device__ __forceinline__ float rnd(float x) { return __uint_as_float(f2tf(x)); }
__device__ __forceinline__ int pidx(int c) {
    return (c & ~7) | ((c & 3) << 1) | ((c >> 2) & 1);
}

__device__ __forceinline__ void mma_tf32(float* d, const uint32_t* a, const uint32_t* b, const float* c) {
    asm("mma.sync.aligned.m16n8k8.row.col.f32.tf32.tf32.f32 "
        "{%0,%1,%2,%3},{%4,%5,%6,%7},{%8,%9},{%10,%11,%12,%13};"
        : "=f"(d[0]), "=f"(d[1]), "=f"(d[2]), "=f"(d[3])
        : "r"(a[0]), "r"(a[1]), "r"(a[2]), "r"(a[3]),
          "r"(b[0]), "r"(b[1]),
          "f"(c[0]), "f"(c[1]), "f"(c[2]), "f"(c[3]));
}
__device__ __forceinline__ void cp16(uint32_t d, const void* s) {
    asm volatile("cp.async.cg.shared.global [%0], [%1], 16;" :: "r"(d), "l"(s));
}
__device__ __forceinline__ void cp16p(uint32_t d, const void* s, int sz) {
    asm volatile("cp.async.cg.shared.global [%0], [%1], 16, %2;" :: "r"(d), "l"(s), "r"(sz));
}
#define CP_COMMIT() asm volatile("cp.async.commit_group;")
#define CP_WAIT2()  asm volatile("cp.async.wait_group 2;")

// ---------------- fused weight prep ----------------
#define S1 (CC*CC)
#define S2 (2*CC*CC)
#define S4 (FF*CC)
#define S6 (KCONV*CC)
__global__ void prep_weights(
    const float* __restrict__ qw, const float* __restrict__ kvw, const float* __restrict__ apw,
    const float* __restrict__ f1w, const float* __restrict__ f2w,
    const float* __restrict__ cqw, const float* __restrict__ cvw,
    float* __restrict__ qwP, float* __restrict__ kvwP, float* __restrict__ apwP,
    float* __restrict__ f1wP, float* __restrict__ f2wP,
    float* __restrict__ cqwP, float* __restrict__ cvwP)
{
    long i = (long)blockIdx.x * 256 + threadIdx.x;
    long o = i;
    if (o < S1) { int n=o/CC, k=o%CC; qwP[(long)n*CC + pidx(k)] = rnd(qw[o]); return; }
    o -= S1;
    if (o < S2) { int n=o/CC, k=o%CC; kvwP[(long)n*CC + pidx(k)] = rnd(kvw[o]); return; }
    o -= S2;
    if (o < S1) { int n=o/CC, k=o%CC; apwP[(long)n*CC + pidx(k)] = rnd(apw[o]); return; }
    o -= S1;
    if (o < S4) { int n=o/CC, k=o%CC; f1wP[(long)n*CC + pidx(k)] = rnd(f1w[o]); return; }
    o -= S4;
    if (o < S4) { int n=o/FF, k=o%FF; f2wP[(long)n*FF + pidx(k)] = rnd(f2w[o]); return; }
    o -= S4;
    if (o < S6) { int oc=o/(CIN*9), rem=o%(CIN*9); int c=rem/9, kk=rem%9;
                  cqwP[(long)oc*KCONV + kk*CIN + pidx(c)] = rnd(cqw[o]); return; }
    o -= S6;
    if (o < S6) { int oc=o/(CIN*9), rem=o%(CIN*9); int c=rem/9, kk=rem%9;
                  cvwP[(long)oc*KCONV + kk*CIN + pidx(c)] = rnd(cvw[o]); return; }
}

// ---------------- NCHW -> NHWC (rounded, c permuted) ----------------
__global__ __launch_bounds__(256) void to_nhwc(const float* __restrict__ in, float* __restrict__ out) {
    __shared__ float tile[32][33];
    int by = blockIdx.z; int b = by >> 7, y = by & 127;
    int c0 = blockIdx.y * 32, x0 = blockIdx.x * 32;
    int tx = threadIdx.x, ty = threadIdx.y;
    #pragma unroll
    for (int i = ty; i < 32; i += 8)
        tile[i][tx] = in[((long)(b * CIN + c0 + i) * HH + y) * WW + x0 + tx];
    __syncthreads();
    #pragma unroll
    for (int i = ty; i < 32; i += 8)
        out[((long)(b * HH + y) * WW + x0 + i) * CIN + pidx(c0 + tx)] = rnd(tile[tx][i]);
}

// ================= tf32 MMA GEMM: block 256x64, warp 64x32, 4-stage pipeline ======
template<bool BIAS, bool GELU, bool ROUND, bool PERMW>
__global__ __launch_bounds__(256, 2) void mm_tf32(
    const float* __restrict__ A, const float* __restrict__ W,
    const float* __restrict__ bias, float* __restrict__ C,
    int M, int N, int K, float alpha)
{
    extern __shared__ float sm_[];
    float* As = sm_;                 // ST * 256*16
    float* Bs = sm_ + ST * AWORDS;   // ST * 64*16
    int tid = threadIdx.x;
    long bm = (long)blockIdx.y * 256;
    int bn = blockIdx.x * 64;
    int wid = tid >> 5, lane = tid & 31;
    int wm = wid >> 1, wn = wid & 1;
    int m0 = wm * 64, n0 = wn * 32;
    int g = lane >> 2, tg = lane & 3;

    int ar = tid >> 2, aseg = tid & 3;
    int asw = aseg ^ (ar & 3);

    uint32_t sAa = (uint32_t)__cvta_generic_to_shared(As);
    uint32_t sBa = (uint32_t)__cvta_generic_to_shared(Bs);
    uint32_t dA = sAa + (ar * 16 + asw * 4) * 4;
    uint32_t dB = sBa + (ar * 16 + asw * 4) * 4;
    const float* pA = A + (bm + ar) * K + aseg * 4;
    const float* pB = W + (long)(bn + ar) * K + aseg * 4;
    const uint32_t stA = AWORDS * 4, stB = BWORDS * 4;
    const uint32_t rA = 64 * 16 * 4;
    const long     gA = (long)64 * K;

    int fo0 = (((tg >> 1) ^ (g & 3)) << 2) + ((tg & 1) << 1);
    int fo1 = fo0 ^ 8;

    float acc[4][4][4];
    #pragma unroll
    for (int i = 0; i < 4; i++)
        #pragma unroll
        for (int j = 0; j < 4; j++)
            #pragma unroll
            for (int r = 0; r < 4; r++) acc[i][j][r] = 0.f;

    int NT = K / 16;
    // prologue: stages 0..2
    #pragma unroll
    for (int s = 0; s < ST - 1; s++) {
        if (s < NT) {
            #pragma unroll
            for (int h = 0; h < 4; h++) cp16(dA + s * stA + h * rA, pA + s * 16 + h * gA);
            cp16(dB + s * stB, pB + s * 16);
        }
        CP_COMMIT();
    }
    for (int t = 0; t < NT; t++) {
        int buf = t & 3;
        CP_WAIT2();
        __syncthreads();
        int tp = t + 3;
        if (tp < NT) {
            int sb = tp & 3;
            #pragma unroll
            for (int h = 0; h < 4; h++) cp16(dA + sb * stA + h * rA, pA + tp * 16 + h * gA);
            cp16(dB + sb * stB, pB + tp * 16);
        }
        CP_COMMIT();
        const float* as = As + buf * AWORDS;
        const float* bs = Bs + buf * BWORDS;
        #pragma unroll
        for (int kk = 0; kk < 2; kk++) {
            int fo = kk ? fo1 : fo0;
            uint32_t af[4][4];
            #pragma unroll
            for (int i = 0; i < 4; i++) {
                float2 aLo = *(const float2*)&as[(m0 + i*16 + g)     * 16 + fo];
                float2 aHi = *(const float2*)&as[(m0 + i*16 + g + 8) * 16 + fo];
                af[i][0] = __float_as_uint(aLo.x); af[i][1] = __float_as_uint(aHi.x);
                af[i][2] = __float_as_uint(aLo.y); af[i][3] = __float_as_uint(aHi.y);
            }
            #pragma unroll
            for (int j = 0; j < 4; j++) {
                float2 bv = *(const float2*)&bs[(n0 + j*8 + g) * 16 + fo];
                uint32_t bf[2] = { __float_as_uint(bv.x), __float_as_uint(bv.y) };
                #pragma unroll
                for (int i = 0; i < 4; i++)
                    mma_tf32(acc[i][j], af[i], bf, acc[i][j]);
            }
        }
    }
    #pragma unroll
    for (int i = 0; i < 4; i++) {
        long row0 = bm + m0 + i * 16 + g;
        #pragma unroll
        for (int j = 0; j < 4; j++) {
            int col = bn + n0 + j * 8 + 2 * tg;
            float b0 = 0.f, b1 = 0.f;
            if (BIAS) { b0 = bias[col]; b1 = bias[col + 1]; }
            #pragma unroll
            for (int half = 0; half < 2; half++) {
                long row = row0 + half * 8;
                float v0 = (acc[i][j][half * 2 + 0] + b0) * alpha;
                float v1 = (acc[i][j][half * 2 + 1] + b1) * alpha;
                if (GELU) {
                    v0 = 0.5f * v0 * (1.f + erff(v0 * 0.70710678118654752f));
                    v1 = 0.5f * v1 * (1.f + erff(v1 * 0.70710678118654752f));
                }
                if (ROUND) { v0 = rnd(v0); v1 = rnd(v1); }
                if (PERMW) {
                    C[row * N + pidx(col)]     = v0;
                    C[row * N + pidx(col + 1)] = v1;
                } else {
                    *(float2*)&C[row * N + col] = make_float2(v0, v1);
                }
            }
        }
    }
}

// ================= conv3x3 implicit GEMM: 256x64, 4-stage pipeline =================
__global__ __launch_bounds__(256, 2) void conv_tf32(
    const float* __restrict__ nhwc, const float* __restrict__ W,
    const float* __restrict__ bias, float* __restrict__ C)
{
    extern __shared__ float sm_[];
    float* As = sm_;
    float* Bs = sm_ + ST * AWORDS;
    const int N = CC;
    int tid = threadIdx.x;
    long bm = (long)blockIdx.y * 256;
    int bn = blockIdx.x * 64;
    int wid = tid >> 5, lane = tid & 31;
    int wm = wid >> 1, wn = wid & 1;
    int m0 = wm * 64, n0 = wn * 32;
    int g = lane >> 2, tg = lane & 3;

    int ar = tid >> 2, aseg = tid & 3;
    int asw = aseg ^ (ar & 3);

    uint32_t sAa = (uint32_t)__cvta_generic_to_shared(As);
    uint32_t sBa = (uint32_t)__cvta_generic_to_shared(Bs);
    uint32_t dA = sAa + (ar * 16 + asw * 4) * 4;
    uint32_t dB = sBa + (ar * 16 + asw * 4) * 4;
    const float* pB = W + (long)(bn + ar) * KCONV + aseg * 4;
    const uint32_t stA = AWORDS * 4, stB = BWORDS * 4;
    const uint32_t rA = 64 * 16 * 4;

    int fo0 = (((tg >> 1) ^ (g & 3)) << 2) + ((tg & 1) << 1);
    int fo1 = fo0 ^ 8;

    // per-row-group: base pointer (at ky=kx=0, i.e. pixel (y-1,x-1)) and 9-bit validity
    const float* base[4];
    int okb[4];
    #pragma unroll
    for (int h = 0; h < 4; h++) {
        long t = bm + ar + h * 64;
        int ix = t & 7, iy = (t >> 3) & 7, wx = (t >> 6) & 15, wy = (t >> 10) & 15;
        int b = (int)(t >> 14);
        int xs = wx * 8 + ix, ys = wy * 8 + iy;
        base[h] = nhwc + ((long)(b * HH + ys - 1) * WW + (xs - 1)) * CIN;
        int m = 0;
        #pragma unroll
        for (int ky = 0; ky < 3; ky++)
            #pragma unroll
            for (int kx = 0; kx < 3; kx++) {
                int sy = ys + ky - 1, sx = xs + kx - 1;
                if (sy >= 0 && sy < HH && sx >= 0 && sx < WW) m |= 1 << (ky * 3 + kx);
            }
        okb[h] = m;
    }

    float acc[4][4][4];
    #pragma unroll
    for (int i = 0; i < 4; i++)
        #pragma unroll
        for (int j = 0; j < 4; j++)
            #pragma unroll
            for (int r = 0; r < 4; r++) acc[i][j][r] = 0.f;

    const int NT = KCONV / 16;   // 54
    // prologue: stages 0..2 (kt = 0,16,32 -> all idx 0, c0 = kt)
    #pragma unroll
    for (int s = 0; s < ST - 1; s++) {
        int c0 = s * 16;
        #pragma unroll
        for (int h = 0; h < 4; h++) {
            bool ok = okb[h] & 1;
            const float* src = ok ? base[h] + c0 + aseg * 4 : nhwc;
            cp16p(dA + s * stA + h * rA, src, ok ? 16 : 0);
        }
        cp16(dB + s * stB, pB + c0);
        CP_COMMIT();
    }
    for (int t = 0; t < NT; t++) {
        int buf = t & 3;
        CP_WAIT2();
        __syncthreads();
        int tp = t + 3;
        if (tp < NT) {
            int sb = tp & 3;
            int kt = tp * 16;
            int idx = kt / 96, c0 = kt - idx * 96;
            int ky = idx / 3, kx = idx - ky * 3;
            long doff = (long)ky * (WW * CIN) + kx * CIN + c0 + aseg * 4;
            #pragma unroll
            for (int h = 0; h < 4; h++) {
                bool ok = (okb[h] >> idx) & 1;
                const float* src = ok ? base[h] + doff : nhwc;
                cp16p(dA + sb * stA + h * rA, src, ok ? 16 : 0);
            }
            cp16(dB + sb * stB, pB + kt);
        }
        CP_COMMIT();
        const float* as = As + buf * AWORDS;
        const float* bs = Bs + buf * BWORDS;
        #pragma unroll
        for (int kk = 0; kk < 2; kk++) {
            int fo = kk ? fo1 : fo0;
            uint32_t af[4][4];
            #pragma unroll
            for (int i = 0; i < 4; i++) {
                float2 aLo = *(const float2*)&as[(m0 + i*16 + g)     * 16 + fo];
                float2 aHi = *(const float2*)&as[(m0 + i*16 + g + 8) * 16 + fo];
                af[i][0] = __float_as_uint(aLo.x); af[i][1] = __float_as_uint(aHi.x);
                af[i][2] = __float_as_uint(aLo.y); af[i][3] = __float_as_uint(aHi.y);
            }
            #pragma unroll
            for (int j = 0; j < 4; j++) {
                float2 bv = *(const float2*)&bs[(n0 + j*8 + g) * 16 + fo];
                uint32_t bf[2] = { __float_as_uint(bv.x), __float_as_uint(bv.y) };
                #pragma unroll
                for (int i = 0; i < 4; i++)
                    mma_tf32(acc[i][j], af[i], bf, acc[i][j]);
            }
        }
    }
    #pragma unroll
    for (int i = 0; i < 4; i++) {
        long row0 = bm + m0 + i * 16 + g;
        #pragma unroll
        for (int j = 0; j < 4; j++) {
            int col = bn + n0 + j * 8 + 2 * tg;
            float b0 = bias[col], b1 = bias[col + 1];
            #pragma unroll
            for (int half = 0; half < 2; half++) {
                long row = row0 + half * 8;
                *(float2*)&C[row * N + col] =
                    make_float2(acc[i][j][half*2+0] + b0, acc[i][j][half*2+1] + b1);
            }
        }
    }
}

// ---------------- windowed attention (reads natural q/kv, writes perm) ----------------
__global__ __launch_bounds__(256) void attn_kernel(
    const float* __restrict__ q, const float* __restrict__ kv,
    const float* __restrict__ rpb, float* __restrict__ out)
{
    __shared__ float qs[64][25], ks[64][25], vs[64][25];
    __shared__ float sc[64][65];
    __shared__ float s_rpb[225][8];
    int w = blockIdx.x;
    int tid = threadIdx.x;
    long tb = (long)w * 64;
    for (int e = tid; e < 225 * 8; e += 256) s_rpb[e >> 3][e & 7] = rpb[e];
    for (int h = 0; h < HEADS; h++) {
        for (int e = tid; e < 64 * 24; e += 256) {
            int p = e / 24, d = e % 24;
            qs[p][d] = q [(tb + p) * CC          + h * HD + d];
            ks[p][d] = kv[(tb + p) * 2 * CC      + h * HD + d];
            vs[p][d] = kv[(tb + p) * 2 * CC + CC + h * HD + d];
        }
        __syncthreads();
        {
            int i = tid >> 2, l = tid & 3;
            #pragma unroll
            for (int jj = 0; jj < 16; jj++) {
                int j = l * 16 + jj;
                float s = 0.f;
                #pragma unroll
                for (int d = 0; d < 24; d++) s += qs[i][d] * ks[j][d];
                int ry = (i >> 3) - (j >> 3) + 7;
                int rx = (i & 7)  - (j & 7)  + 7;
                s += s_rpb[ry * 15 + rx][h];
                sc[i][j] = s;
            }
            float mx = -1e30f;
            #pragma unroll
            for (int jj = 0; jj < 16; jj++) mx = fmaxf(mx, sc[i][l * 16 + jj]);
            mx = fmaxf(mx, __shfl_xor_sync(~0u, mx, 1));
            mx = fmaxf(mx, __shfl_xor_sync(~0u, mx, 2));
            float sum = 0.f;
            #pragma unroll
            for (int jj = 0; jj < 16; jj++) {
                float e_ = __expf(sc[i][l * 16 + jj] - mx);
                sc[i][l * 16 + jj] = e_; sum += e_;
            }
            sum += __shfl_xor_sync(~0u, sum, 1);
            sum += __shfl_xor_sync(~0u, sum, 2);
            float inv = 1.f / sum;
            #pragma unroll
            for (int jj = 0; jj < 16; jj++) sc[i][l * 16 + jj] *= inv;
        }
        __syncthreads();
        for (int e = tid; e < 64 * 24; e += 256) {
            int p = e / 24, d = e % 24;
            float s = 0.f;
            #pragma unroll
            for (int j = 0; j < 64; j++) s += sc[p][j] * vs[j][d];
            out[(tb + p) * CC + pidx(h * HD + d)] = rnd(s);
        }
        __syncthreads();
    }
}

// ---------------- row LN ----------------
template<bool ROUND, bool PERM>
__global__ __launch_bounds__(256) void ln_rows_kernel(
    const float* __restrict__ in, const float* __restrict__ gamma,
    const float* __restrict__ beta, float* __restrict__ out)
{
    int warp = threadIdx.x >> 5, lane = threadIdx.x & 31;
    long row = (long)blockIdx.x * 8 + warp;
    const float* p = in + row * CC;
    float v[6];
    float sum = 0.f, sq = 0.f;
    #pragma unroll
    for (int k = 0; k < 6; k++) { v[k] = p[lane + k * 32]; sum += v[k]; sq += v[k] * v[k]; }
    #pragma unroll
    for (int o = 16; o > 0; o >>= 1) { sum += __shfl_xor_sync(~0u, sum, o); sq += __shfl_xor_sync(~0u, sq, o); }
    float mean = sum * (1.f / CC), var = sq * (1.f / CC) - mean * mean;
    float rstd = rsqrtf(var + 1e-5f);
    float* qo = out + row * CC;
    #pragma unroll
    for (int k = 0; k < 6; k++) {
        int c = lane + k * 32;
        float r = (v[k] - mean) * rstd * gamma[c] + beta[c];
        if (ROUND) r = rnd(r);
        qo[PERM ? pidx(c) : c] = r;
    }
}

// ---------------- token layout -> NCHW with residual ----------------
__global__ __launch_bounds__(256) void final_kernel(
    const float* __restrict__ mln, const float* __restrict__ xp,
    const float* __restrict__ vp, float* __restrict__ out)
{
    __shared__ float s[128][33];
    int bx = blockIdx.x;
    int cch = bx % 6;
    int by = bx / 6;
    int b = by >> 7, y = by & 127;
    int c0 = cch * 32;
    int tid = threadIdx.x;
    int wy = y >> 3, iy = y & 7;
    #pragma unroll
    for (int it = 0; it < 16; it++) {
        int e = tid + it * 256;
        int x = e >> 5, cl = e & 31;
        long t = (long)b * 16384 + (wy * 16 + (x >> 3)) * 64 + iy * 8 + (x & 7);
        long a = t * CC + c0 + cl;
        s[x][cl] = mln[a] + xp[a] + vp[a];
    }
    __syncthreads();
    #pragma unroll
    for (int it = 0; it < 16; it++) {
        int e = tid + it * 256;
        int x = e & 127, c = e >> 7;
        out[((long)(b * CC + c0 + c) * HH + y) * WW + x] = s[x][c];
    }
}

extern "C" void kernel_launch(void* const* d_in, const int* in_sizes, int n_in,
                              void* d_out, int out_size)
{
    const float* x    = (const float*)d_in[0];
    const float* v    = (const float*)d_in[1];
    const float* pq_w = (const float*)d_in[2];
    const float* pq_b = (const float*)d_in[3];
    const float* pv_w = (const float*)d_in[4];
    const float* pv_b = (const float*)d_in[5];
    const float* n1w  = (const float*)d_in[6];
    const float* n1b  = (const float*)d_in[7];
    const float* n2w  = (const float*)d_in[8];
    const float* n2b  = (const float*)d_in[9];
    const float* n3w  = (const float*)d_in[10];
    const float* n3b  = (const float*)d_in[11];
    const float* n4w  = (const float*)d_in[12];
    const float* n4b  = (const float*)d_in[13];
    const float* qw   = (const float*)d_in[14];
    const float* kvw  = (const float*)d_in[15];
    const float* apw  = (const float*)d_in[16];
    const float* apb  = (const float*)d_in[17];
    const float* rpb  = (const float*)d_in[18];
    const float* f1w  = (const float*)d_in[19];
    const float* f1b  = (const float*)d_in[20];
    const float* f2w  = (const float*)d_in[21];
    const float* f2b  = (const float*)d_in[22];
    float* out = (float*)d_out;
    (void)in_sizes; (void)n_in; (void)out_size;

    float *nx,*nv,*xp,*vp,*xs,*vs,*q,*kv,*at,*pr,*l3,*h1,*m,*l4;
    float *qwP,*kvwP,*apwP,*f1wP,*f2wP,*cqwP,*cvwP;
    cudaGetSymbolAddress((void**)&nx, g_nx);
    cudaGetSymbolAddress((void**)&nv, g_nv);
    cudaGetSymbolAddress((void**)&xp, g_xp);
    cudaGetSymbolAddress((void**)&vp, g_vp);
    cudaGetSymbolAddress((void**)&xs, g_xs);
    cudaGetSymbolAddress((void**)&vs, g_vs);
    cudaGetSymbolAddress((void**)&q , g_q );
    cudaGetSymbolAddress((void**)&kv, g_kv);
    cudaGetSymbolAddress((void**)&at, g_at);
    cudaGetSymbolAddress((void**)&pr, g_pr);
    cudaGetSymbolAddress((void**)&l3, g_l3);
    cudaGetSymbolAddress((void**)&h1, g_h1);
    cudaGetSymbolAddress((void**)&m , g_m );
    cudaGetSymbolAddress((void**)&l4, g_l4);
    cudaGetSymbolAddress((void**)&qwP , g_qwP );
    cudaGetSymbolAddress((void**)&kvwP, g_kvwP);
    cudaGetSymbolAddress((void**)&apwP, g_apwP);
    cudaGetSymbolAddress((void**)&f1wP, g_f1wP);
    cudaGetSymbolAddress((void**)&f2wP, g_f2wP);
    cudaGetSymbolAddress((void**)&cqwP, g_cqwP);
    cudaGetSymbolAddress((void**)&cvwP, g_cvwP);

    const float SCALE = 0.20412414523193154f;  // 24^-0.5

    // opt-in to >48KB dynamic smem (idempotent; safe under graph capture)
    cudaFuncSetAttribute(mm_tf32<false,false,false,false>, cudaFuncAttributeMaxDynamicSharedMemorySize, SMEMB);
    cudaFuncSetAttribute(mm_tf32<true ,false,false,false>, cudaFuncAttributeMaxDynamicSharedMemorySize, SMEMB);
    cudaFuncSetAttribute(mm_tf32<true ,true ,true ,true >, cudaFuncAttributeMaxDynamicSharedMemorySize, SMEMB);
    cudaFuncSetAttribute(conv_tf32, cudaFuncAttributeMaxDynamicSharedMemorySize, SMEMB);

    long totalW = (long)S1 + S2 + S1 + S4 + S4 + S6 + S6;
    prep_weights<<<(int)((totalW + 255) / 256), 256>>>(
        qw, kvw, apw, f1w, f2w, pq_w, pv_w,
        qwP, kvwP, apwP, f1wP, f2wP, cqwP, cvwP);

    to_nhwc<<<dim3(4,3,1024),dim3(32,8)>>>(x, nx);
    to_nhwc<<<dim3(4,3,1024),dim3(32,8)>>>(v, nv);

    conv_tf32<<<dim3(3,512),256,SMEMB>>>(nx, cqwP, pq_b, xp);
    conv_tf32<<<dim3(3,512),256,SMEMB>>>(nv, cvwP, pv_b, vp);

    ln_rows_kernel<true,true><<<16384,256>>>(xp, n1w, n1b, xs);
    ln_rows_kernel<true,true><<<16384,256>>>(vp, n2w, n2b, vs);

    mm_tf32<false,false,false,false><<<dim3(3,512),256,SMEMB>>>(xs, qwP , nullptr, q , TT, CC,   CC, SCALE);
    mm_tf32<false,false,false,false><<<dim3(6,512),256,SMEMB>>>(vs, kvwP, nullptr, kv, TT, 2*CC, CC, 1.f);

    attn_kernel<<<2048,256>>>(q, kv, rpb, at);

    mm_tf32<true,false,false,false><<<dim3(3,512),256,SMEMB>>>(at, apwP, apb, pr, TT, CC, CC, 1.f);

    ln_rows_kernel<true,true><<<16384,256>>>(pr, n3w, n3b, l3);

    mm_tf32<true,true ,true ,true ><<<dim3(12,512),256,SMEMB>>>(l3, f1wP, f1b, h1, TT, FF, CC, 1.f);
    mm_tf32<true,false,false,false><<<dim3(3,512),256,SMEMB>>>(h1, f2wP, f2b, m , TT, CC, FF, 2.f);

    ln_rows_kernel<false,false><<<16384,256>>>(m, n4w, n4b, l4);

    final_kernel<<<6144,256>>>(l4, xp, vp, out);
}

// round 8
// speedup vs baseline: 1.2644x; 1.1652x over previous
#include <cuda_runtime.h>
#include <math.h>
#include <stdint.h>

#define BB 8
#define CIN 96
#define CC 192
#define HH 128
#define WW 128
#define WS 8
#define HEADS 8
#define HD 24
#define TT 131072
#define FF 768
#define KCONV 864   // 9*96

// pipeline
#define ST 4
#define AWORDS (256*16)
#define BWORDS (64*16)
#define SMEMB (ST*(AWORDS+BWORDS)*4)

// ---------------- scratch ----------------
__device__ float g_nx[BB*CIN*HH*WW];
__device__ float g_nv[BB*CIN*HH*WW];
__device__ float g_xp[TT*CC];
__device__ float g_vp[TT*CC];
__device__ float g_xs[TT*CC];
__device__ float g_vs[TT*CC];
__device__ float g_q [TT*CC];
__device__ float g_kv[TT*2*CC];
__device__ float g_at[TT*CC];
__device__ float g_pr[TT*CC];
__device__ float g_l3[TT*CC];
__device__ float g_h1[(long)TT*FF];
__device__ float g_m [TT*CC];
__device__ float g_l4[TT*CC];
// weights: n-major, k-contiguous, k permuted in (k,k+4) pairs, tf32-rounded
__device__ float g_qwP [CC*CC];
__device__ float g_kvwP[2*CC*CC];
__device__ float g_apwP[CC*CC];
__device__ float g_f1wP[FF*CC];
__device__ float g_f2wP[CC*FF];
__device__ float g_cqwP[CC*KCONV];
__device__ float g_cvwP[CC*KCONV];

// ---------------- helpers ----------------
__device__ __forceinline__ uint32_t f2tf(float x) {
    uint32_t r; asm("cvt.rna.tf32.f32 %0, %1;" : "=r"(r) : "f"(x)); return r;
}
__device__ __forceinline__ float rnd(float x) { return __uint_as_float(f2tf(x)); }
__device__ __forceinline__ int pidx(int c) {
    return (c & ~7) | ((c & 3) << 1) | ((c >> 2) & 1);
}

__device__ __forceinline__ void mma_tf32(float* d, const uint32_t* a, const uint32_t* b, const float* c) {
    asm("mma.sync.aligned.m16n8k8.row.col.f32.tf32.tf32.f32 "
        "{%0,%1,%2,%3},{%4,%5,%6,%7},{%8,%9},{%10,%11,%12,%13};"
        : "=f"(d[0]), "=f"(d[1]), "=f"(d[2]), "=f"(d[3])
        : "r"(a[0]), "r"(a[1]), "r"(a[2]), "r"(a[3]),
          "r"(b[0]), "r"(b[1]),
          "f"(c[0]), "f"(c[1]), "f"(c[2]), "f"(c[3]));
}
__device__ __forceinline__ void cp16(uint32_t d, const void* s) {
    asm volatile("cp.async.cg.shared.global [%0], [%1], 16;" :: "r"(d), "l"(s));
}
__device__ __forceinline__ void cp16p(uint32_t d, const void* s, int sz) {
    asm volatile("cp.async.cg.shared.global [%0], [%1], 16, %2;" :: "r"(d), "l"(s), "r"(sz));
}
#define CP_COMMIT() asm volatile("cp.async.commit_group;")
#define CP_WAIT2()  asm volatile("cp.async.wait_group 2;")

// ---------------- fused weight prep ----------------
#define S1 (CC*CC)
#define S2 (2*CC*CC)
#define S4 (FF*CC)
#define S6 (KCONV*CC)
__global__ void prep_weights(
    const float* __restrict__ qw, const float* __restrict__ kvw, const float* __restrict__ apw,
    const float* __restrict__ f1w, const float* __restrict__ f2w,
    const float* __restrict__ cqw, const float* __restrict__ cvw,
    float* __restrict__ qwP, float* __restrict__ kvwP, float* __restrict__ apwP,
    float* __restrict__ f1wP, float* __restrict__ f2wP,
    float* __restrict__ cqwP, float* __restrict__ cvwP)
{
    long i = (long)blockIdx.x * 256 + threadIdx.x;
    long o = i;
    if (o < S1) { int n=o/CC, k=o%CC; qwP[(long)n*CC + pidx(k)] = rnd(qw[o]); return; }
    o -= S1;
    if (o < S2) { int n=o/CC, k=o%CC; kvwP[(long)n*CC + pidx(k)] = rnd(kvw[o]); return; }
    o -= S2;
    if (o < S1) { int n=o/CC, k=o%CC; apwP[(long)n*CC + pidx(k)] = rnd(apw[o]); return; }
    o -= S1;
    if (o < S4) { int n=o/CC, k=o%CC; f1wP[(long)n*CC + pidx(k)] = rnd(f1w[o]); return; }
    o -= S4;
    if (o < S4) { int n=o/FF, k=o%FF; f2wP[(long)n*FF + pidx(k)] = rnd(f2w[o]); return; }
    o -= S4;
    if (o < S6) { int oc=o/(CIN*9), rem=o%(CIN*9); int c=rem/9, kk=rem%9;
                  cqwP[(long)oc*KCONV + kk*CIN + pidx(c)] = rnd(cqw[o]); return; }
    o -= S6;
    if (o < S6) { int oc=o/(CIN*9), rem=o%(CIN*9); int c=rem/9, kk=rem%9;
                  cvwP[(long)oc*KCONV + kk*CIN + pidx(c)] = rnd(cvw[o]); return; }
}

// ---------------- NCHW -> NHWC (rounded, c permuted) ----------------
__global__ __launch_bounds__(256) void to_nhwc(const float* __restrict__ in, float* __restrict__ out) {
    __shared__ float tile[32][33];
    int by = blockIdx.z; int b = by >> 7, y = by & 127;
    int c0 = blockIdx.y * 32, x0 = blockIdx.x * 32;
    int tx = threadIdx.x, ty = threadIdx.y;
    #pragma unroll
    for (int i = ty; i < 32; i += 8)
        tile[i][tx] = in[((long)(b * CIN + c0 + i) * HH + y) * WW + x0 + tx];
    __syncthreads();
    #pragma unroll
    for (int i = ty; i < 32; i += 8)
        out[((long)(b * HH + y) * WW + x0 + i) * CIN + pidx(c0 + tx)] = rnd(tile[tx][i]);
}

// ================= tf32 MMA GEMM: block 256x64, warp 64x32, 4-stage pipeline ======
template<bool BIAS, bool GELU, bool ROUND, bool PERMW>
__global__ __launch_bounds__(256, 2) void mm_tf32(
    const float* __restrict__ A, const float* __restrict__ W,
    const float* __restrict__ bias, float* __restrict__ C,
    int M, int N, int K, float alpha)
{
    extern __shared__ float sm_[];
    float* As = sm_;
    float* Bs = sm_ + ST * AWORDS;
    int tid = threadIdx.x;
    long bm = (long)blockIdx.y * 256;
    int bn = blockIdx.x * 64;
    int wid = tid >> 5, lane = tid & 31;
    int wm = wid >> 1, wn = wid & 1;
    int m0 = wm * 64, n0 = wn * 32;
    int g = lane >> 2, tg = lane & 3;

    int ar = tid >> 2, aseg = tid & 3;
    int asw = aseg ^ (ar & 3);

    uint32_t sAa = (uint32_t)__cvta_generic_to_shared(As);
    uint32_t sBa = (uint32_t)__cvta_generic_to_shared(Bs);
    uint32_t dA = sAa + (ar * 16 + asw * 4) * 4;
    uint32_t dB = sBa + (ar * 16 + asw * 4) * 4;
    const float* pA = A + (bm + ar) * K + aseg * 4;
    const float* pB = W + (long)(bn + ar) * K + aseg * 4;
    const uint32_t stA = AWORDS * 4, stB = BWORDS * 4;
    const uint32_t rA = 64 * 16 * 4;
    const long     gA = (long)64 * K;

    int fo0 = (((tg >> 1) ^ (g & 3)) << 2) + ((tg & 1) << 1);
    int fo1 = fo0 ^ 8;

    float acc[4][4][4];
    #pragma unroll
    for (int i = 0; i < 4; i++)
        #pragma unroll
        for (int j = 0; j < 4; j++)
            #pragma unroll
            for (int r = 0; r < 4; r++) acc[i][j][r] = 0.f;

    int NT = K / 16;
    #pragma unroll
    for (int s = 0; s < ST - 1; s++) {
        if (s < NT) {
            #pragma unroll
            for (int h = 0; h < 4; h++) cp16(dA + s * stA + h * rA, pA + s * 16 + h * gA);
            cp16(dB + s * stB, pB + s * 16);
        }
        CP_COMMIT();
    }
    for (int t = 0; t < NT; t++) {
        int buf = t & 3;
        CP_WAIT2();
        __syncthreads();
        int tp = t + 3;
        if (tp < NT) {
            int sb = tp & 3;
            #pragma unroll
            for (int h = 0; h < 4; h++) cp16(dA + sb * stA + h * rA, pA + tp * 16 + h * gA);
            cp16(dB + sb * stB, pB + tp * 16);
        }
        CP_COMMIT();
        const float* as = As + buf * AWORDS;
        const float* bs = Bs + buf * BWORDS;
        #pragma unroll
        for (int kk = 0; kk < 2; kk++) {
            int fo = kk ? fo1 : fo0;
            uint32_t af[4][4];
            #pragma unroll
            for (int i = 0; i < 4; i++) {
                float2 aLo = *(const float2*)&as[(m0 + i*16 + g)     * 16 + fo];
                float2 aHi = *(const float2*)&as[(m0 + i*16 + g + 8) * 16 + fo];
                af[i][0] = __float_as_uint(aLo.x); af[i][1] = __float_as_uint(aHi.x);
                af[i][2] = __float_as_uint(aLo.y); af[i][3] = __float_as_uint(aHi.y);
            }
            #pragma unroll
            for (int j = 0; j < 4; j++) {
                float2 bv = *(const float2*)&bs[(n0 + j*8 + g) * 16 + fo];
                uint32_t bf[2] = { __float_as_uint(bv.x), __float_as_uint(bv.y) };
                #pragma unroll
                for (int i = 0; i < 4; i++)
                    mma_tf32(acc[i][j], af[i], bf, acc[i][j]);
            }
        }
    }
    #pragma unroll
    for (int i = 0; i < 4; i++) {
        long row0 = bm + m0 + i * 16 + g;
        #pragma unroll
        for (int j = 0; j < 4; j++) {
            int col = bn + n0 + j * 8 + 2 * tg;
            float b0 = 0.f, b1 = 0.f;
            if (BIAS) { b0 = bias[col]; b1 = bias[col + 1]; }
            #pragma unroll
            for (int half = 0; half < 2; half++) {
                long row = row0 + half * 8;
                float v0 = (acc[i][j][half * 2 + 0] + b0) * alpha;
                float v1 = (acc[i][j][half * 2 + 1] + b1) * alpha;
                if (GELU) {
                    v0 = 0.5f * v0 * (1.f + erff(v0 * 0.70710678118654752f));
                    v1 = 0.5f * v1 * (1.f + erff(v1 * 0.70710678118654752f));
                }
                if (ROUND) { v0 = rnd(v0); v1 = rnd(v1); }
                if (PERMW) {
                    C[row * N + pidx(col)]     = v0;
                    C[row * N + pidx(col + 1)] = v1;
                } else {
                    *(float2*)&C[row * N + col] = make_float2(v0, v1);
                }
            }
        }
    }
}

// ================= conv3x3 implicit GEMM: 256x64, 4-stage pipeline =================
__global__ __launch_bounds__(256, 2) void conv_tf32(
    const float* __restrict__ nhwc, const float* __restrict__ W,
    const float* __restrict__ bias, float* __restrict__ C)
{
    extern __shared__ float sm_[];
    float* As = sm_;
    float* Bs = sm_ + ST * AWORDS;
    const int N = CC;
    int tid = threadIdx.x;
    long bm = (long)blockIdx.y * 256;
    int bn = blockIdx.x * 64;
    int wid = tid >> 5, lane = tid & 31;
    int wm = wid >> 1, wn = wid & 1;
    int m0 = wm * 64, n0 = wn * 32;
    int g = lane >> 2, tg = lane & 3;

    int ar = tid >> 2, aseg = tid & 3;
    int asw = aseg ^ (ar & 3);

    uint32_t sAa = (uint32_t)__cvta_generic_to_shared(As);
    uint32_t sBa = (uint32_t)__cvta_generic_to_shared(Bs);
    uint32_t dA = sAa + (ar * 16 + asw * 4) * 4;
    uint32_t dB = sBa + (ar * 16 + asw * 4) * 4;
    const float* pB = W + (long)(bn + ar) * KCONV + aseg * 4;
    const uint32_t stA = AWORDS * 4, stB = BWORDS * 4;
    const uint32_t rA = 64 * 16 * 4;

    int fo0 = (((tg >> 1) ^ (g & 3)) << 2) + ((tg & 1) << 1);
    int fo1 = fo0 ^ 8;

    const float* base[4];
    int okb[4];
    #pragma unroll
    for (int h = 0; h < 4; h++) {
        long t = bm + ar + h * 64;
        int ix = t & 7, iy = (t >> 3) & 7, wx = (t >> 6) & 15, wy = (t >> 10) & 15;
        int b = (int)(t >> 14);
        int xs = wx * 8 + ix, ys = wy * 8 + iy;
        base[h] = nhwc + ((long)(b * HH + ys - 1) * WW + (xs - 1)) * CIN;
        int m = 0;
        #pragma unroll
        for (int ky = 0; ky < 3; ky++)
            #pragma unroll
            for (int kx = 0; kx < 3; kx++) {
                int sy = ys + ky - 1, sx = xs + kx - 1;
                if (sy >= 0 && sy < HH && sx >= 0 && sx < WW) m |= 1 << (ky * 3 + kx);
            }
        okb[h] = m;
    }

    float acc[4][4][4];
    #pragma unroll
    for (int i = 0; i < 4; i++)
        #pragma unroll
        for (int j = 0; j < 4; j++)
            #pragma unroll
            for (int r = 0; r < 4; r++) acc[i][j][r] = 0.f;

    const int NT = KCONV / 16;   // 54
    #pragma unroll
    for (int s = 0; s < ST - 1; s++) {
        int c0 = s * 16;
        #pragma unroll
        for (int h = 0; h < 4; h++) {
            bool ok = okb[h] & 1;
            const float* src = ok ? base[h] + c0 + aseg * 4 : nhwc;
            cp16p(dA + s * stA + h * rA, src, ok ? 16 : 0);
        }
        cp16(dB + s * stB, pB + c0);
        CP_COMMIT();
    }
    for (int t = 0; t < NT; t++) {
        int buf = t & 3;
        CP_WAIT2();
        __syncthreads();
        int tp = t + 3;
        if (tp < NT) {
            int sb = tp & 3;
            int kt = tp * 16;
            int idx = kt / 96, c0 = kt - idx * 96;
            int ky = idx / 3, kx = idx - ky * 3;
            long doff = (long)ky * (WW * CIN) + kx * CIN + c0 + aseg * 4;
            #pragma unroll
            for (int h = 0; h < 4; h++) {
                bool ok = (okb[h] >> idx) & 1;
                const float* src = ok ? base[h] + doff : nhwc;
                cp16p(dA + sb * stA + h * rA, src, ok ? 16 : 0);
            }
            cp16(dB + sb * stB, pB + kt);
        }
        CP_COMMIT();
        const float* as = As + buf * AWORDS;
        const float* bs = Bs + buf * BWORDS;
        #pragma unroll
        for (int kk = 0; kk < 2; kk++) {
            int fo = kk ? fo1 : fo0;
            uint32_t af[4][4];
            #pragma unroll
            for (int i = 0; i < 4; i++) {
                float2 aLo = *(const float2*)&as[(m0 + i*16 + g)     * 16 + fo];
                float2 aHi = *(const float2*)&as[(m0 + i*16 + g + 8) * 16 + fo];
                af[i][0] = __float_as_uint(aLo.x); af[i][1] = __float_as_uint(aHi.x);
                af[i][2] = __float_as_uint(aLo.y); af[i][3] = __float_as_uint(aHi.y);
            }
            #pragma unroll
            for (int j = 0; j < 4; j++) {
                float2 bv = *(const float2*)&bs[(n0 + j*8 + g) * 16 + fo];
                uint32_t bf[2] = { __float_as_uint(bv.x), __float_as_uint(bv.y) };
                #pragma unroll
                for (int i = 0; i < 4; i++)
                    mma_tf32(acc[i][j], af[i], bf, acc[i][j]);
            }
        }
    }
    #pragma unroll
    for (int i = 0; i < 4; i++) {
        long row0 = bm + m0 + i * 16 + g;
        #pragma unroll
        for (int j = 0; j < 4; j++) {
            int col = bn + n0 + j * 8 + 2 * tg;
            float b0 = bias[col], b1 = bias[col + 1];
            #pragma unroll
            for (int half = 0; half < 2; half++) {
                long row = row0 + half * 8;
                *(float2*)&C[row * N + col] =
                    make_float2(acc[i][j][half*2+0] + b0, acc[i][j][half*2+1] + b1);
            }
        }
    }
}

// ---------------- windowed attention: vectorized, register scores ----------------
// block = 1 window (256 thr). thread (i = tid>>2, l = tid&3) owns q-row i, j in {4*jj+l}.
// K/V/Q per-head tiles double-buffered via cp.async; scores & softmax fully in regs.
#define ATQ0 0
#define ATK0 12288
#define ATV0 24576
#define ATRP 36864
__global__ __launch_bounds__(256) void attn_kernel(
    const float* __restrict__ q, const float* __restrict__ kv,
    const float* __restrict__ rpb, float* __restrict__ out)
{
    __shared__ __align__(16) char smem[36864 + 7200];
    uint32_t sb = (uint32_t)__cvta_generic_to_shared(smem);
    float* s_rpb = (float*)(smem + ATRP);
    int w = blockIdx.x;
    int tid = threadIdx.x;
    long tb = (long)w * 64;

    for (int e = tid; e < 225 * 8; e += 256) s_rpb[e] = rpb[e];

    auto loadh = [&](int h, int s) {
        #pragma unroll
        for (int it = 0; it < 2; it++) {
            int idx = tid + it * 256;
            if (idx < 384) {
                int p = idx / 6, d4 = idx - p * 6;
                const float* qg = q  + (tb + p) * CC     + h * HD + d4 * 4;
                const float* kg = kv + (tb + p) * 2 * CC + h * HD + d4 * 4;
                uint32_t off = s * 6144 + idx * 16;
                cp16(sb + ATQ0 + off, qg);
                cp16(sb + ATK0 + off, kg);
                cp16(sb + ATV0 + off, kg + CC);
            }
        }
        CP_COMMIT();
    };
    loadh(0, 0);

    int i = tid >> 2, l = tid & 3;
    int iy = i >> 3, ixx = i & 7;

    for (int h = 0; h < HEADS; h++) {
        int s = h & 1;
        __syncthreads();                      // prev compute done -> safe to refill other buf
        if (h + 1 < HEADS) {
            loadh(h + 1, s ^ 1);
            asm volatile("cp.async.wait_group 1;" ::: "memory");
        } else {
            asm volatile("cp.async.wait_group 0;" ::: "memory");
        }
        __syncthreads();                      // head h data visible to all

        const float4* sQ = (const float4*)(smem + s * 6144);
        const float4* sK = (const float4*)(smem + ATK0 + s * 6144);
        const float4* sV = (const float4*)(smem + ATV0 + s * 6144);

        float4 q4[6];
        #pragma unroll
        for (int d4 = 0; d4 < 6; d4++) q4[d4] = sQ[i * 6 + d4];

        float sreg[16];
        #pragma unroll
        for (int jj = 0; jj < 16; jj++) {
            int j = jj * 4 + l;
            float acc = 0.f;
            #pragma unroll
            for (int d4 = 0; d4 < 6; d4++) {
                float4 k4 = sK[j * 6 + d4];
                acc = fmaf(q4[d4].x, k4.x, acc);
                acc = fmaf(q4[d4].y, k4.y, acc);
                acc = fmaf(q4[d4].z, k4.z, acc);
                acc = fmaf(q4[d4].w, k4.w, acc);
            }
            int ry = iy - (j >> 3) + 7;
            int rx = ixx - (j & 7) + 7;
            sreg[jj] = acc + s_rpb[(ry * 15 + rx) * 8 + h];
        }
        float mx = sreg[0];
        #pragma unroll
        for (int jj = 1; jj < 16; jj++) mx = fmaxf(mx, sreg[jj]);
        mx = fmaxf(mx, __shfl_xor_sync(~0u, mx, 1));
        mx = fmaxf(mx, __shfl_xor_sync(~0u, mx, 2));
        float sum = 0.f;
        #pragma unroll
        for (int jj = 0; jj < 16; jj++) { sreg[jj] = __expf(sreg[jj] - mx); sum += sreg[jj]; }
        sum += __shfl_xor_sync(~0u, sum, 1);
        sum += __shfl_xor_sync(~0u, sum, 2);
        float inv = 1.f / sum;

        float oa[24];
        #pragma unroll
        for (int d = 0; d < 24; d++) oa[d] = 0.f;
        #pragma unroll
        for (int jj = 0; jj < 16; jj++) {
            int j = jj * 4 + l;
            float p = sreg[jj] * inv;
            #pragma unroll
            for (int d4 = 0; d4 < 6; d4++) {
                float4 v4 = sV[j * 6 + d4];
                oa[d4*4+0] = fmaf(p, v4.x, oa[d4*4+0]);
                oa[d4*4+1] = fmaf(p, v4.y, oa[d4*4+1]);
                oa[d4*4+2] = fmaf(p, v4.z, oa[d4*4+2]);
                oa[d4*4+3] = fmaf(p, v4.w, oa[d4*4+3]);
            }
        }
        #pragma unroll
        for (int d = 0; d < 24; d++) {
            oa[d] += __shfl_xor_sync(~0u, oa[d], 1);
            oa[d] += __shfl_xor_sync(~0u, oa[d], 2);
        }
        long ob = (tb + i) * CC;
        #pragma unroll
        for (int dd = 0; dd < 6; dd++) {
            int d = l * 6 + dd;
            out[ob + pidx(h * HD + d)] = rnd(oa[d]);
        }
    }
}

// ---------------- row LN ----------------
template<bool ROUND, bool PERM>
__global__ __launch_bounds__(256) void ln_rows_kernel(
    const float* __restrict__ in, const float* __restrict__ gamma,
    const float* __restrict__ beta, float* __restrict__ out)
{
    int warp = threadIdx.x >> 5, lane = threadIdx.x & 31;
    long row = (long)blockIdx.x * 8 + warp;
    const float* p = in + row * CC;
    float v[6];
    float sum = 0.f, sq = 0.f;
    #pragma unroll
    for (int k = 0; k < 6; k++) { v[k] = p[lane + k * 32]; sum += v[k]; sq += v[k] * v[k]; }
    #pragma unroll
    for (int o = 16; o > 0; o >>= 1) { sum += __shfl_xor_sync(~0u, sum, o); sq += __shfl_xor_sync(~0u, sq, o); }
    float mean = sum * (1.f / CC), var = sq * (1.f / CC) - mean * mean;
    float rstd = rsqrtf(var + 1e-5f);
    float* qo = out + row * CC;
    #pragma unroll
    for (int k = 0; k < 6; k++) {
        int c = lane + k * 32;
        float r = (v[k] - mean) * rstd * gamma[c] + beta[c];
        if (ROUND) r = rnd(r);
        qo[PERM ? pidx(c) : c] = r;
    }
}

// ---------------- token layout -> NCHW with residual ----------------
__global__ __launch_bounds__(256) void final_kernel(
    const float* __restrict__ mln, const float* __restrict__ xp,
    const float* __restrict__ vp, float* __restrict__ out)
{
    __shared__ float s[128][33];
    int bx = blockIdx.x;
    int cch = bx % 6;
    int by = bx / 6;
    int b = by >> 7, y = by & 127;
    int c0 = cch * 32;
    int tid = threadIdx.x;
    int wy = y >> 3, iy = y & 7;
    #pragma unroll
    for (int it = 0; it < 16; it++) {
        int e = tid + it * 256;
        int x = e >> 5, cl = e & 31;
        long t = (long)b * 16384 + (wy * 16 + (x >> 3)) * 64 + iy * 8 + (x & 7);
        long a = t * CC + c0 + cl;
        s[x][cl] = mln[a] + xp[a] + vp[a];
    }
    __syncthreads();
    #pragma unroll
    for (int it = 0; it < 16; it++) {
        int e = tid + it * 256;
        int x = e & 127, c = e >> 7;
        out[((long)(b * CC + c0 + c) * HH + y) * WW + x] = s[x][c];
    }
}

extern "C" void kernel_launch(void* const* d_in, const int* in_sizes, int n_in,
                              void* d_out, int out_size)
{
    const float* x    = (const float*)d_in[0];
    const float* v    = (const float*)d_in[1];
    const float* pq_w = (const float*)d_in[2];
    const float* pq_b = (const float*)d_in[3];
    const float* pv_w = (const float*)d_in[4];
    const float* pv_b = (const float*)d_in[5];
    const float* n1w  = (const float*)d_in[6];
    const float* n1b  = (const float*)d_in[7];
    const float* n2w  = (const float*)d_in[8];
    const float* n2b  = (const float*)d_in[9];
    const float* n3w  = (const float*)d_in[10];
    const float* n3b  = (const float*)d_in[11];
    const float* n4w  = (const float*)d_in[12];
    const float* n4b  = (const float*)d_in[13];
    const float* qw   = (const float*)d_in[14];
    const float* kvw  = (const float*)d_in[15];
    const float* apw  = (const float*)d_in[16];
    const float* apb  = (const float*)d_in[17];
    const float* rpb  = (const float*)d_in[18];
    const float* f1w  = (const float*)d_in[19];
    const float* f1b  = (const float*)d_in[20];
    const float* f2w  = (const float*)d_in[21];
    const float* f2b  = (const float*)d_in[22];
    float* out = (float*)d_out;
    (void)in_sizes; (void)n_in; (void)out_size;

    float *nx,*nv,*xp,*vp,*xs,*vs,*q,*kv,*at,*pr,*l3,*h1,*m,*l4;
    float *qwP,*kvwP,*apwP,*f1wP,*f2wP,*cqwP,*cvwP;
    cudaGetSymbolAddress((void**)&nx, g_nx);
    cudaGetSymbolAddress((void**)&nv, g_nv);
    cudaGetSymbolAddress((void**)&xp, g_xp);
    cudaGetSymbolAddress((void**)&vp, g_vp);
    cudaGetSymbolAddress((void**)&xs, g_xs);
    cudaGetSymbolAddress((void**)&vs, g_vs);
    cudaGetSymbolAddress((void**)&q , g_q );
    cudaGetSymbolAddress((void**)&kv, g_kv);
    cudaGetSymbolAddress((void**)&at, g_at);
    cudaGetSymbolAddress((void**)&pr, g_pr);
    cudaGetSymbolAddress((void**)&l3, g_l3);
    cudaGetSymbolAddress((void**)&h1, g_h1);
    cudaGetSymbolAddress((void**)&m , g_m );
    cudaGetSymbolAddress((void**)&l4, g_l4);
    cudaGetSymbolAddress((void**)&qwP , g_qwP );
    cudaGetSymbolAddress((void**)&kvwP, g_kvwP);
    cudaGetSymbolAddress((void**)&apwP, g_apwP);
    cudaGetSymbolAddress((void**)&f1wP, g_f1wP);
    cudaGetSymbolAddress((void**)&f2wP, g_f2wP);
    cudaGetSymbolAddress((void**)&cqwP, g_cqwP);
    cudaGetSymbolAddress((void**)&cvwP, g_cvwP);

    const float SCALE = 0.20412414523193154f;  // 24^-0.5

    cudaFuncSetAttribute(mm_tf32<false,false,false,false>, cudaFuncAttributeMaxDynamicSharedMemorySize, SMEMB);
    cudaFuncSetAttribute(mm_tf32<true ,false,false,false>, cudaFuncAttributeMaxDynamicSharedMemorySize, SMEMB);
    cudaFuncSetAttribute(mm_tf32<true ,true ,true ,true >, cudaFuncAttributeMaxDynamicSharedMemorySize, SMEMB);
    cudaFuncSetAttribute(conv_tf32, cudaFuncAttributeMaxDynamicSharedMemorySize, SMEMB);

    long totalW = (long)S1 + S2 + S1 + S4 + S4 + S6 + S6;
    prep_weights<<<(int)((totalW + 255) / 256), 256>>>(
        qw, kvw, apw, f1w, f2w, pq_w, pv_w,
        qwP, kvwP, apwP, f1wP, f2wP, cqwP, cvwP);

    to_nhwc<<<dim3(4,3,1024),dim3(32,8)>>>(x, nx);
    to_nhwc<<<dim3(4,3,1024),dim3(32,8)>>>(v, nv);

    conv_tf32<<<dim3(3,512),256,SMEMB>>>(nx, cqwP, pq_b, xp);
    conv_tf32<<<dim3(3,512),256,SMEMB>>>(nv, cvwP, pv_b, vp);

    ln_rows_kernel<true,true><<<16384,256>>>(xp, n1w, n1b, xs);
    ln_rows_kernel<true,true><<<16384,256>>>(vp, n2w, n2b, vs);

    mm_tf32<false,false,false,false><<<dim3(3,512),256,SMEMB>>>(xs, qwP , nullptr, q , TT, CC,   CC, SCALE);
    mm_tf32<false,false,false,false><<<dim3(6,512),256,SMEMB>>>(vs, kvwP, nullptr, kv, TT, 2*CC, CC, 1.f);

    attn_kernel<<<2048,256>>>(q, kv, rpb, at);

    mm_tf32<true,false,false,false><<<dim3(3,512),256,SMEMB>>>(at, apwP, apb, pr, TT, CC, CC, 1.f);

    ln_rows_kernel<true,true><<<16384,256>>>(pr, n3w, n3b, l3);

    mm_tf32<true,true ,true ,true ><<<dim3(12,512),256,SMEMB>>>(l3, f1wP, f1b, h1, TT, FF, CC, 1.f);
    mm_tf32<true,false,false,false><<<dim3(3,512),256,SMEMB>>>(h1, f2wP, f2b, m , TT, CC, FF, 2.f);

    ln_rows_kernel<false,false><<<16384,256>>>(m, n4w, n4b, l4);

    final_kernel<<<6144,256>>>(l4, xp, vp, out);
}